// round 4
// baseline (speedup 1.0000x reference)
#include <cuda_runtime.h>
#include <cuda_fp16.h>
#include <math.h>
#include <stdint.h>

// ---------------------------------------------------------------------------
// Problem constants
// ---------------------------------------------------------------------------
#define NN      8192
#define MREAL   101
#define MP      128
#define PITER   30
#define KSPLIT  2
#define KCHUNK  (NN / KSPLIT)        // 4096
#define KT      32                   // k per pipeline stage
#define KITERS  (KCHUNK / KT)        // 128
#define NSTG    4
#define A_B     (128 * KT * 2)       // 8192 B per A plane (128 rows x 32 k fp16)
#define B_B     (64 * KT * 2)        // 4096 B per B plane (64 cols x 32 k fp16)
#define STAGE_B (2 * A_B + 2 * B_B)  // 24576 B: Ahi, Alo, Bhi, Blo
#define SMEM_DYN (NSTG * STAGE_B)    // 98304 B

// ---------------------------------------------------------------------------
// Scratch (static device globals; no allocation allowed)
// ---------------------------------------------------------------------------
__device__ __half g_Khi16[(size_t)NN * NN];     // 128 MB
__device__ __half g_Klo16[(size_t)NN * NN];     // 128 MB
__device__ __half g_Ph16[(size_t)MP * NN];      // scaled P hi, col-major
__device__ __half g_Pl16[(size_t)MP * NN];      // scaled P lo
__device__ float  g_R[(size_t)MP * NN];
__device__ float  g_X[NN];
__device__ float  g_rs[MP];
__device__ float  g_pscale[MP];                 // power-of-2 column scale
__device__ float  g_Vpart[(size_t)KSPLIT * MP * NN];  // 8 MB
__device__ float  g_alpha[PITER * MP];
__device__ float  g_beta[PITER * MP];
__device__ float  g_logdet;

// ---------------------------------------------------------------------------
// PTX helpers (family-portable only: ldmatrix / mma.sync / cp.async)
// ---------------------------------------------------------------------------
__device__ __forceinline__ uint32_t smem_u32(const void* p) {
    uint32_t a;
    asm("{ .reg .u64 t; cvta.to.shared.u64 t, %1; cvt.u32.u64 %0, t; }"
        : "=r"(a) : "l"(p));
    return a;
}

__device__ __forceinline__ void ldsm_x4(uint32_t (&r)[4], uint32_t addr) {
    asm volatile("ldmatrix.sync.aligned.m8n8.x4.shared.b16 {%0,%1,%2,%3}, [%4];"
        : "=r"(r[0]), "=r"(r[1]), "=r"(r[2]), "=r"(r[3]) : "r"(addr));
}

__device__ __forceinline__ void mma16816(float (&d)[4], const uint32_t (&a)[4],
                                         uint32_t b0, uint32_t b1) {
    asm volatile("mma.sync.aligned.m16n8k16.row.col.f32.f16.f16.f32 "
        "{%0,%1,%2,%3}, {%4,%5,%6,%7}, {%8,%9}, {%0,%1,%2,%3};"
        : "+f"(d[0]), "+f"(d[1]), "+f"(d[2]), "+f"(d[3])
        : "r"(a[0]), "r"(a[1]), "r"(a[2]), "r"(a[3]), "r"(b0), "r"(b1));
}

#define CPASYNC16(dst, src) \
    asm volatile("cp.async.cg.shared.global [%0], [%1], 16;" \
                 :: "r"(dst), "l"(__cvta_generic_to_global(src)) : "memory")

// Conflict-free swizzle for 64B rows (r = row, ch = 16B chunk 0..3)
#define SWZ(r, ch) (((r) << 6) + ((((ch) ^ (((r) >> 1) & 3))) << 4))

// ---------------------------------------------------------------------------
// Reductions
// ---------------------------------------------------------------------------
template <int BS>
__device__ __forceinline__ float blockReduce(float v, float* red) {
    int tid = threadIdx.x;
    red[tid] = v;
    __syncthreads();
#pragma unroll
    for (int s = BS / 2; s > 0; s >>= 1) {
        if (tid < s) red[tid] += red[tid + s];
        __syncthreads();
    }
    float out = red[0];
    __syncthreads();
    return out;
}

// 1024-thread reduce: shfl within warp, one smem stage, 2 barriers total.
__device__ __forceinline__ float fastReduce1024(float v, float* red, float* bcast) {
    int lane = threadIdx.x & 31, wid = threadIdx.x >> 5;
#pragma unroll
    for (int o = 16; o > 0; o >>= 1) v += __shfl_xor_sync(0xFFFFFFFFu, v, o);
    if (lane == 0) red[wid] = v;
    __syncthreads();
    if (wid == 0) {
        float x = red[lane];
#pragma unroll
        for (int o = 16; o > 0; o >>= 1) x += __shfl_xor_sync(0xFFFFFFFFu, x, o);
        if (lane == 0) *bcast = x;
    }
    __syncthreads();
    return *bcast;
}

// ---------------------------------------------------------------------------
// Split K into fp16 hi + fp16 lo (once per launch)
// ---------------------------------------------------------------------------
__global__ void k_split(const float* __restrict__ K) {
    size_t i0 = (size_t)blockIdx.x * blockDim.x + threadIdx.x;
    size_t stride = (size_t)gridDim.x * blockDim.x;
    size_t n8 = (size_t)NN * NN / 8;
    for (size_t i = i0; i < n8; i += stride) {
        float4 a = ((const float4*)K)[2 * i];
        float4 b = ((const float4*)K)[2 * i + 1];
        float v[8] = {a.x, a.y, a.z, a.w, b.x, b.y, b.z, b.w};
        union { __half h[8]; uint4 u; } H, L;
#pragma unroll
        for (int j = 0; j < 8; j++) {
            __half hh = __float2half_rn(v[j]);
            H.h[j] = hh;
            L.h[j] = __float2half_rn(v[j] - __half2float(hh));
        }
        ((uint4*)g_Khi16)[i] = H.u;
        ((uint4*)g_Klo16)[i] = L.u;
    }
}

// ---------------------------------------------------------------------------
// Init: B = [y | Z | 0-pad]; Ph/Pl = fp16 split of B (scale 1), R = B, X = 0
// ---------------------------------------------------------------------------
__global__ void k_init(const float* __restrict__ y, const float* __restrict__ Z) {
    int stride = gridDim.x * blockDim.x;
    for (int idx = blockIdx.x * blockDim.x + threadIdx.x; idx < MP * NN; idx += stride) {
        int col = idx >> 13;
        int row = idx & (NN - 1);
        float v = 0.0f;
        if (col == 0)        v = y[row];
        else if (col <= 100) v = Z[row * 100 + (col - 1)];
        __half h = __float2half_rn(v);
        g_Ph16[idx] = h;
        g_Pl16[idx] = __float2half_rn(v - __half2float(h));
        g_R[idx] = v;
        if (col == 0) g_X[row] = 0.0f;
        if (idx < MP) g_pscale[idx] = 1.0f;
    }
}

__global__ void k_rsinit() {
    __shared__ float red[256];
    int j = blockIdx.x;
    const float* p = g_R + (size_t)j * NN;
    float s = 0.0f;
    for (int i = threadIdx.x; i < NN; i += 256) s += p[i] * p[i];
    s = blockReduce<256>(s, red);
    if (threadIdx.x == 0) g_rs[j] = s;
}

// ---------------------------------------------------------------------------
// fp16-split HMMA GEMM, 128x64 CTA tile, 2 CTAs/SM.
// grid: bid = ksp*128 + colb*64 + rowblock. 3 products, fp32 accumulate.
// ---------------------------------------------------------------------------
__device__ __forceinline__ void issue_stage(uint32_t sb, int s, int rb, int cb,
                                            int k0, int tid) {
    uint32_t st = sb + s * STAGE_B;
    // A planes: 512 chunks each, 2 per thread
#pragma unroll
    for (int m = 0; m < 2; m++) {
        int idx = m * 256 + tid;
        int r = idx >> 2, ch = idx & 3;
        uint32_t d = st + SWZ(r, ch);
        const __half* pa = g_Khi16 + (size_t)(rb + r) * NN + k0 + ch * 8;
        const __half* pb = g_Klo16 + (size_t)(rb + r) * NN + k0 + ch * 8;
        CPASYNC16(d, pa);
        CPASYNC16(d + A_B, pb);
    }
    // B planes: 256 chunks each, 1 per thread
    {
        int r = tid >> 2, ch = tid & 3;
        uint32_t d = st + 2 * A_B + SWZ(r, ch);
        const __half* pc = g_Ph16 + (size_t)(cb + r) * NN + k0 + ch * 8;
        const __half* pd = g_Pl16 + (size_t)(cb + r) * NN + k0 + ch * 8;
        CPASYNC16(d, pc);
        CPASYNC16(d + B_B, pd);
    }
    asm volatile("cp.async.commit_group;" ::: "memory");
}

__global__ void __launch_bounds__(256, 2) k_gemm_mma() {
    extern __shared__ char smem[];
    uint32_t sb = smem_u32(smem);
    int tid = threadIdx.x, lane = tid & 31, w = tid >> 5;
    int wm = w & 3, wn = w >> 2;          // 4 m-bands x 2 n-bands
    int bid = blockIdx.x;
    int rb = (bid & 63) * 128;
    int cb = ((bid >> 6) & 1) * 64;
    int ksp = bid >> 7;
    int kbase = ksp * KCHUNK;

    float acc[2][4][4];
#pragma unroll
    for (int mi = 0; mi < 2; mi++)
#pragma unroll
        for (int nj = 0; nj < 4; nj++)
#pragma unroll
            for (int q = 0; q < 4; q++) acc[mi][nj][q] = 0.0f;

    issue_stage(sb, 0, rb, cb, kbase, tid);
    issue_stage(sb, 1, rb, cb, kbase + KT, tid);
    issue_stage(sb, 2, rb, cb, kbase + 2 * KT, tid);

    int rA = wm * 32 + (lane & 15);
    int rB = wn * 32 + (lane & 15);
    int chHalf = lane >> 4;

    for (int t = 0; t < KITERS; t++) {
        if (t < KITERS - 2)       asm volatile("cp.async.wait_group 2;" ::: "memory");
        else if (t == KITERS - 2) asm volatile("cp.async.wait_group 1;" ::: "memory");
        else                      asm volatile("cp.async.wait_group 0;" ::: "memory");
        __syncthreads();
        if (t + 3 < KITERS) issue_stage(sb, (t + 3) & 3, rb, cb, kbase + (t + 3) * KT, tid);

        uint32_t st = sb + (t & 3) * STAGE_B;
#pragma unroll
        for (int kk = 0; kk < 2; kk++) {
            int ch = kk * 2 + chHalf;
            uint32_t ah[2][4], al[2][4], bh[2][4], bl[2][4];
            ldsm_x4(ah[0], st + SWZ(rA, ch));
            ldsm_x4(ah[1], st + SWZ(rA + 16, ch));
            ldsm_x4(al[0], st + A_B + SWZ(rA, ch));
            ldsm_x4(al[1], st + A_B + SWZ(rA + 16, ch));
            ldsm_x4(bh[0], st + 2 * A_B + SWZ(rB, ch));
            ldsm_x4(bh[1], st + 2 * A_B + SWZ(rB + 16, ch));
            ldsm_x4(bl[0], st + 2 * A_B + B_B + SWZ(rB, ch));
            ldsm_x4(bl[1], st + 2 * A_B + B_B + SWZ(rB + 16, ch));
#pragma unroll
            for (int mi = 0; mi < 2; mi++)
#pragma unroll
                for (int nj = 0; nj < 4; nj++) {
                    int g = nj >> 1, sel = nj & 1;
                    uint32_t b0 = bh[g][sel], b1 = bh[g][sel + 2];
                    uint32_t c0 = bl[g][sel], c1 = bl[g][sel + 2];
                    mma16816(acc[mi][nj], ah[mi], b0, b1);
                    mma16816(acc[mi][nj], ah[mi], c0, c1);
                    mma16816(acc[mi][nj], al[mi], b0, b1);
                }
        }
    }

    // epilogue: scatter fp32 accumulators to Vpart (col-major [col][row])
    float* vp = g_Vpart + (size_t)ksp * MP * NN;
    int row0 = rb + wm * 32 + (lane >> 2);
    int col0 = cb + wn * 32 + (lane & 3) * 2;
#pragma unroll
    for (int mi = 0; mi < 2; mi++)
#pragma unroll
        for (int nj = 0; nj < 4; nj++) {
            int r_ = row0 + mi * 16;
            int c_ = col0 + nj * 8;
            vp[(size_t)c_ * NN + r_]           = acc[mi][nj][0];
            vp[(size_t)(c_ + 1) * NN + r_]     = acc[mi][nj][1];
            vp[(size_t)c_ * NN + r_ + 8]       = acc[mi][nj][2];
            vp[(size_t)(c_ + 1) * NN + r_ + 8] = acc[mi][nj][3];
        }
}

// ---------------------------------------------------------------------------
// CG update: one block (1024 threads) per real column, vectorized,
// shuffle-based reductions, power-of-2 column scaling.
// ---------------------------------------------------------------------------
__global__ void k_update(int it) {
    __shared__ float red[32];
    __shared__ float bc;
    const int E4 = NN / 4 / 1024;   // 2 float4 iterations

    int j = blockIdx.x;
    int tid = threadIdx.x;
    float c = g_pscale[j];
    const float4* V0 = (const float4*)(g_Vpart + (size_t)j * NN);
    const float4* V1 = (const float4*)(g_Vpart + ((size_t)MP + j) * NN);
    const float4* R4 = (const float4*)(g_R + (size_t)j * NN);
    const uint2* Ph2 = (const uint2*)(g_Ph16 + (size_t)j * NN);
    const uint2* Pl2 = (const uint2*)(g_Pl16 + (size_t)j * NN);

    float4 p[E4], v[E4], r[E4];
    float pv = 0.0f;
#pragma unroll
    for (int t = 0; t < E4; t++) {
        int i4 = t * 1024 + tid;
        float4 a = V0[i4], b = V1[i4];
        float4 s = make_float4(a.x + b.x, a.y + b.y, a.z + b.z, a.w + b.w);
        v[t] = s;
        uint2 hu = Ph2[i4], lu = Pl2[i4];
        __half2 h0 = *(__half2*)&hu.x, h1 = *(__half2*)&hu.y;
        __half2 l0 = *(__half2*)&lu.x, l1 = *(__half2*)&lu.y;
        float2 f0 = __half22float2(h0), f1 = __half22float2(h1);
        float2 g0 = __half22float2(l0), g1 = __half22float2(l1);
        float4 pp = make_float4(f0.x + g0.x, f0.y + g0.y, f1.x + g1.x, f1.y + g1.y);
        p[t] = pp;
        pv += pp.x * s.x + pp.y * s.y + pp.z * s.z + pp.w * s.w;
    }
    pv = fastReduce1024(pv, red, &bc);         // = c^2 * (P.V)
    float rs_old = g_rs[j];
    float alpha = rs_old * c * c / pv;         // true alpha
    float aoc = alpha / c;

    float rr = 0.0f;
#pragma unroll
    for (int t = 0; t < E4; t++) {
        int i4 = t * 1024 + tid;
        float4 rv = R4[i4];
        rv.x -= aoc * v[t].x; rv.y -= aoc * v[t].y;
        rv.z -= aoc * v[t].z; rv.w -= aoc * v[t].w;
        r[t] = rv;
        rr += rv.x * rv.x + rv.y * rv.y + rv.z * rv.z + rv.w * rv.w;
    }
    if (j == 0) {
        float4* X4 = (float4*)g_X;
#pragma unroll
        for (int t = 0; t < E4; t++) {
            int i4 = t * 1024 + tid;
            float4 x = X4[i4];
            x.x += aoc * p[t].x; x.y += aoc * p[t].y;
            x.z += aoc * p[t].z; x.w += aoc * p[t].w;
            X4[i4] = x;
        }
    }
    rr = fastReduce1024(rr, red, &bc);
    float beta = rr / rs_old;
    float c2 = exp2f(-rintf(0.5f * log2f(rr * (1.0f / (float)NN))));
    if (tid == 0) {
        g_rs[j] = rr;
        g_alpha[it * MP + j] = alpha;
        g_beta[it * MP + j]  = beta;
        g_pscale[j] = c2;
    }
    float boc = beta / c;

    uint2* Phw = (uint2*)(g_Ph16 + (size_t)j * NN);
    uint2* Plw = (uint2*)(g_Pl16 + (size_t)j * NN);
    float4* Rw = (float4*)(g_R + (size_t)j * NN);
#pragma unroll
    for (int t = 0; t < E4; t++) {
        int i4 = t * 1024 + tid;
        float pn[4] = {
            r[t].x + boc * p[t].x, r[t].y + boc * p[t].y,
            r[t].z + boc * p[t].z, r[t].w + boc * p[t].w };
        __half hh[4]; float ll[4];
#pragma unroll
        for (int q = 0; q < 4; q++) {
            float ps = c2 * pn[q];
            hh[q] = __float2half_rn(ps);
            ll[q] = ps - __half2float(hh[q]);
        }
        uint2 hu, lu;
        __half2 t0 = __halves2half2(hh[0], hh[1]);
        __half2 t1 = __halves2half2(hh[2], hh[3]);
        hu.x = *(uint32_t*)&t0; hu.y = *(uint32_t*)&t1;
        __half2 u0 = __floats2half2_rn(ll[0], ll[1]);
        __half2 u1 = __floats2half2_rn(ll[2], ll[3]);
        lu.x = *(uint32_t*)&u0; lu.y = *(uint32_t*)&u1;
        Phw[i4] = hu;
        Plw[i4] = lu;
        Rw[i4] = r[t];
    }
}

// ---------------------------------------------------------------------------
// SLQ logdet (TQLI on 30x30 tridiagonal, first-row eigenvector weights)
// ---------------------------------------------------------------------------
__device__ void tqli30(double* d, double* e, double* z) {
    const int n = PITER;
    for (int l = 0; l < n; l++) {
        int iter = 0;
        int m;
        do {
            for (m = l; m < n - 1; m++) {
                double dd = fabs(d[m]) + fabs(d[m + 1]);
                if (fabs(e[m]) <= 2.3e-16 * dd) break;
            }
            if (m != l) {
                if (iter++ == 64) break;
                double g = (d[l + 1] - d[l]) / (2.0 * e[l]);
                double rr = sqrt(g * g + 1.0);
                double sg = (g >= 0.0) ? rr : -rr;
                g = d[m] - d[l] + e[l] / (g + sg);
                double s = 1.0, cc = 1.0, p = 0.0;
                bool under = false;
                for (int i = m - 1; i >= l; i--) {
                    double f = s * e[i];
                    double b = cc * e[i];
                    double rq = sqrt(f * f + g * g);
                    e[i + 1] = rq;
                    if (rq == 0.0) {
                        d[i + 1] -= p;
                        e[m] = 0.0;
                        under = true;
                        break;
                    }
                    s = f / rq; cc = g / rq;
                    g = d[i + 1] - p;
                    rq = (d[i] - g) * s + 2.0 * cc * b;
                    p = s * rq;
                    d[i + 1] = g + p;
                    g = cc * rq - b;
                    double zi = z[i], zi1 = z[i + 1];
                    z[i + 1] = s * zi + cc * zi1;
                    z[i]     = cc * zi - s * zi1;
                }
                if (under) continue;
                d[l] -= p;
                e[l] = g;
                e[m] = 0.0;
            }
        } while (m != l);
    }
}

__global__ void k_logdet() {
    __shared__ double qsum[128];
    int tid = threadIdx.x;
    double quad = 0.0;
    if (tid < 100) {
        int j = tid + 1;
        double d[PITER], e[PITER], z[PITER];
        double pa = 1.0, pb = 0.0;
        for (int k = 0; k < PITER; k++) {
            double a = (double)g_alpha[k * MP + j];
            double b = (double)g_beta[k * MP + j];
            d[k] = 1.0 / a + ((k > 0) ? pb / pa : 0.0);
            e[k] = (k < PITER - 1) ? sqrt(b) / a : 0.0;
            z[k] = (k == 0) ? 1.0 : 0.0;
            pa = a; pb = b;
        }
        tqli30(d, e, z);
        for (int k = 0; k < PITER; k++) {
            double lam = d[k] < 1e-12 ? 1e-12 : d[k];
            quad += z[k] * z[k] * log(lam);
        }
    }
    qsum[tid] = quad;
    __syncthreads();
    if (tid == 0) {
        double s = 0.0;
        for (int i = 0; i < 100; i++) s += qsum[i];
        g_logdet = (float)((double)NN * s / 100.0);
    }
}

__global__ void k_final(const float* __restrict__ y, float* __restrict__ out) {
    __shared__ float red[256];
    float s = 0.0f;
    for (int i = threadIdx.x; i < NN; i += 256) s += y[i] * g_X[i];
    s = blockReduce<256>(s, red);
    if (threadIdx.x == 0) {
        const double LOG2PI = 1.8378770664093454836;
        double r = -0.5 * (double)s - 0.5 * (double)g_logdet - 0.5 * (double)NN * LOG2PI;
        out[0] = (float)r;
    }
}

// ---------------------------------------------------------------------------
// Launch
// ---------------------------------------------------------------------------
extern "C" void kernel_launch(void* const* d_in, const int* in_sizes, int n_in,
                              void* d_out, int out_size) {
    const float* K = (const float*)d_in[0];
    const float* y = (const float*)d_in[1];
    const float* Z = (const float*)d_in[2];
    float* out = (float*)d_out;

    cudaFuncSetAttribute(k_gemm_mma, cudaFuncAttributeMaxDynamicSharedMemorySize, SMEM_DYN);

    k_split<<<4096, 256>>>(K);
    k_init<<<512, 256>>>(y, Z);
    k_rsinit<<<MREAL, 256>>>();
    for (int it = 0; it < PITER; it++) {
        k_gemm_mma<<<256, 256, SMEM_DYN>>>();
        k_update<<<MREAL, 1024>>>(it);
    }
    k_logdet<<<1, 128>>>();
    k_final<<<1, 256>>>(y, out);
}

// round 5
// speedup vs baseline: 1.2609x; 1.2609x over previous
#include <cuda_runtime.h>
#include <cuda_fp16.h>
#include <math.h>
#include <stdint.h>

// ---------------------------------------------------------------------------
// Problem constants
// ---------------------------------------------------------------------------
#define NN      8192
#define MREAL   101
#define MP      128
#define PITER   30
#define KSPLIT  2
#define KCHUNK  (NN / KSPLIT)        // 4096
#define KT      32                   // k per pipeline stage
#define KITERS  (KCHUNK / KT)        // 128
#define NSTG    4
#define PLANE_B (128 * KT * 2)       // 8192 B per plane (128 rows/cols x 32 k fp16)
#define STAGE_B (3 * PLANE_B)        // 24576 B: Ahi, Bhi, Blo
#define SMEM_DYN (NSTG * STAGE_B)    // 98304 B

// ---------------------------------------------------------------------------
// Scratch (static device globals; no allocation allowed)
// ---------------------------------------------------------------------------
__device__ __half g_Khi16[(size_t)NN * NN];     // 128 MB: fp16-rounded K
__device__ __half g_Ph16[(size_t)MP * NN];      // scaled P hi, col-major
__device__ __half g_Pl16[(size_t)MP * NN];      // scaled P lo
__device__ float  g_R[(size_t)MP * NN];
__device__ float  g_X[NN];
__device__ float  g_rs[MP];
__device__ float  g_pscale[MP];                 // power-of-2 column scale
__device__ float  g_Vpart[(size_t)KSPLIT * MP * NN];  // 8 MB
__device__ float  g_alpha[PITER * MP];
__device__ float  g_beta[PITER * MP];
__device__ float  g_logdet;

// ---------------------------------------------------------------------------
// PTX helpers (family-portable only: ldmatrix / mma.sync / cp.async)
// ---------------------------------------------------------------------------
__device__ __forceinline__ uint32_t smem_u32(const void* p) {
    uint32_t a;
    asm("{ .reg .u64 t; cvta.to.shared.u64 t, %1; cvt.u32.u64 %0, t; }"
        : "=r"(a) : "l"(p));
    return a;
}

__device__ __forceinline__ void ldsm_x4(uint32_t (&r)[4], uint32_t addr) {
    asm volatile("ldmatrix.sync.aligned.m8n8.x4.shared.b16 {%0,%1,%2,%3}, [%4];"
        : "=r"(r[0]), "=r"(r[1]), "=r"(r[2]), "=r"(r[3]) : "r"(addr));
}

__device__ __forceinline__ void mma16816(float (&d)[4], const uint32_t (&a)[4],
                                         uint32_t b0, uint32_t b1) {
    asm volatile("mma.sync.aligned.m16n8k16.row.col.f32.f16.f16.f32 "
        "{%0,%1,%2,%3}, {%4,%5,%6,%7}, {%8,%9}, {%0,%1,%2,%3};"
        : "+f"(d[0]), "+f"(d[1]), "+f"(d[2]), "+f"(d[3])
        : "r"(a[0]), "r"(a[1]), "r"(a[2]), "r"(a[3]), "r"(b0), "r"(b1));
}

#define CPASYNC16(dst, src) \
    asm volatile("cp.async.cg.shared.global [%0], [%1], 16;" \
                 :: "r"(dst), "l"(__cvta_generic_to_global(src)) : "memory")

// Conflict-free swizzle for 64B rows (r = row, ch = 16B chunk 0..3)
#define SWZ(r, ch) (((r) << 6) + ((((ch) ^ (((r) >> 1) & 3))) << 4))

// ---------------------------------------------------------------------------
// Reductions
// ---------------------------------------------------------------------------
template <int BS>
__device__ __forceinline__ float blockReduce(float v, float* red) {
    int tid = threadIdx.x;
    red[tid] = v;
    __syncthreads();
#pragma unroll
    for (int s = BS / 2; s > 0; s >>= 1) {
        if (tid < s) red[tid] += red[tid + s];
        __syncthreads();
    }
    float out = red[0];
    __syncthreads();
    return out;
}

__device__ __forceinline__ float fastReduce1024(float v, float* red, float* bcast) {
    int lane = threadIdx.x & 31, wid = threadIdx.x >> 5;
#pragma unroll
    for (int o = 16; o > 0; o >>= 1) v += __shfl_xor_sync(0xFFFFFFFFu, v, o);
    if (lane == 0) red[wid] = v;
    __syncthreads();
    if (wid == 0) {
        float x = red[lane];
#pragma unroll
        for (int o = 16; o > 0; o >>= 1) x += __shfl_xor_sync(0xFFFFFFFFu, x, o);
        if (lane == 0) *bcast = x;
    }
    __syncthreads();
    return *bcast;
}

// ---------------------------------------------------------------------------
// Round K to fp16 (once per launch)
// ---------------------------------------------------------------------------
__global__ void k_split(const float* __restrict__ K) {
    size_t i0 = (size_t)blockIdx.x * blockDim.x + threadIdx.x;
    size_t stride = (size_t)gridDim.x * blockDim.x;
    size_t n8 = (size_t)NN * NN / 8;
    for (size_t i = i0; i < n8; i += stride) {
        float4 a = ((const float4*)K)[2 * i];
        float4 b = ((const float4*)K)[2 * i + 1];
        union { __half h[8]; uint4 u; } H;
        H.h[0] = __float2half_rn(a.x); H.h[1] = __float2half_rn(a.y);
        H.h[2] = __float2half_rn(a.z); H.h[3] = __float2half_rn(a.w);
        H.h[4] = __float2half_rn(b.x); H.h[5] = __float2half_rn(b.y);
        H.h[6] = __float2half_rn(b.z); H.h[7] = __float2half_rn(b.w);
        ((uint4*)g_Khi16)[i] = H.u;
    }
}

// ---------------------------------------------------------------------------
// Init: B = [y | Z | 0-pad]; Ph/Pl = fp16 split of B (scale 1), R = B, X = 0
// ---------------------------------------------------------------------------
__global__ void k_init(const float* __restrict__ y, const float* __restrict__ Z) {
    int stride = gridDim.x * blockDim.x;
    for (int idx = blockIdx.x * blockDim.x + threadIdx.x; idx < MP * NN; idx += stride) {
        int col = idx >> 13;
        int row = idx & (NN - 1);
        float v = 0.0f;
        if (col == 0)        v = y[row];
        else if (col <= 100) v = Z[row * 100 + (col - 1)];
        __half h = __float2half_rn(v);
        g_Ph16[idx] = h;
        g_Pl16[idx] = __float2half_rn(v - __half2float(h));
        g_R[idx] = v;
        if (col == 0) g_X[row] = 0.0f;
        if (idx < MP) g_pscale[idx] = 1.0f;
    }
}

__global__ void k_rsinit() {
    __shared__ float red[256];
    int j = blockIdx.x;
    const float* p = g_R + (size_t)j * NN;
    float s = 0.0f;
    for (int i = threadIdx.x; i < NN; i += 256) s += p[i] * p[i];
    s = blockReduce<256>(s, red);
    if (threadIdx.x == 0) g_rs[j] = s;
}

// ---------------------------------------------------------------------------
// HMMA GEMM: Vpart[ksp] = Khi[rb:rb+128, kchunk] @ (Phi + Plo)
// CTA tile 128x128, warp tile 64x32 (2m x 4n warps), 2 MMA products.
// grid = 64 rowblocks x KSPLIT = 128 CTAs, 1 per SM.
// ---------------------------------------------------------------------------
__device__ __forceinline__ void issue_stage(uint32_t sb, int s, int rb, int k0, int tid) {
    uint32_t st = sb + s * STAGE_B;
#pragma unroll
    for (int m = 0; m < 2; m++) {
        int idx = m * 256 + tid;
        int r = idx >> 2, ch = idx & 3;
        uint32_t d = st + SWZ(r, ch);
        CPASYNC16(d, g_Khi16 + (size_t)(rb + r) * NN + k0 + ch * 8);
        CPASYNC16(d + PLANE_B, g_Ph16 + (size_t)r * NN + k0 + ch * 8);
        CPASYNC16(d + 2 * PLANE_B, g_Pl16 + (size_t)r * NN + k0 + ch * 8);
    }
    asm volatile("cp.async.commit_group;" ::: "memory");
}

__global__ void __launch_bounds__(256) k_gemm_mma() {
    extern __shared__ char smem[];
    uint32_t sb = smem_u32(smem);
    int tid = threadIdx.x, lane = tid & 31, w = tid >> 5;
    int wm = w & 1, wn = w >> 1;          // 2 m-bands x 4 n-bands
    int bid = blockIdx.x;
    int rb = (bid & 63) * 128;
    int ksp = bid >> 6;
    int kbase = ksp * KCHUNK;

    float acc[4][4][4];
#pragma unroll
    for (int mi = 0; mi < 4; mi++)
#pragma unroll
        for (int nj = 0; nj < 4; nj++)
#pragma unroll
            for (int q = 0; q < 4; q++) acc[mi][nj][q] = 0.0f;

    issue_stage(sb, 0, rb, kbase, tid);
    issue_stage(sb, 1, rb, kbase + KT, tid);
    issue_stage(sb, 2, rb, kbase + 2 * KT, tid);

    int rA = wm * 64 + (lane & 15);
    int rB = wn * 32 + (lane & 15);
    int chHalf = lane >> 4;

    for (int t = 0; t < KITERS; t++) {
        if (t < KITERS - 2)       asm volatile("cp.async.wait_group 2;" ::: "memory");
        else if (t == KITERS - 2) asm volatile("cp.async.wait_group 1;" ::: "memory");
        else                      asm volatile("cp.async.wait_group 0;" ::: "memory");
        __syncthreads();
        if (t + 3 < KITERS) issue_stage(sb, (t + 3) & 3, rb, kbase + (t + 3) * KT, tid);

        uint32_t st = sb + (t & 3) * STAGE_B;

        // load operand regs for both k16 halves up-front (kk1 loads hide
        // behind kk0 MMAs), then run the two MMA blocks.
        uint32_t ah[2][4][4], bh[2][2][4], bl[2][2][4];
#pragma unroll
        for (int kk = 0; kk < 2; kk++) {
            int ch = kk * 2 + chHalf;
#pragma unroll
            for (int i = 0; i < 4; i++)
                ldsm_x4(ah[kk][i], st + SWZ(rA + i * 16, ch));
            ldsm_x4(bh[kk][0], st + PLANE_B + SWZ(rB, ch));
            ldsm_x4(bh[kk][1], st + PLANE_B + SWZ(rB + 16, ch));
            ldsm_x4(bl[kk][0], st + 2 * PLANE_B + SWZ(rB, ch));
            ldsm_x4(bl[kk][1], st + 2 * PLANE_B + SWZ(rB + 16, ch));
        }
#pragma unroll
        for (int kk = 0; kk < 2; kk++) {
#pragma unroll
            for (int mi = 0; mi < 4; mi++)
#pragma unroll
                for (int nj = 0; nj < 4; nj++) {
                    int g = nj >> 1, sel = nj & 1;
                    mma16816(acc[mi][nj], ah[kk][mi],
                             bh[kk][g][sel], bh[kk][g][sel + 2]);
                    mma16816(acc[mi][nj], ah[kk][mi],
                             bl[kk][g][sel], bl[kk][g][sel + 2]);
                }
        }
    }

    // epilogue: scatter fp32 accumulators to Vpart (col-major [col][row])
    float* vp = g_Vpart + (size_t)ksp * MP * NN;
    int row0 = rb + wm * 64 + (lane >> 2);
    int col0 = wn * 32 + (lane & 3) * 2;
#pragma unroll
    for (int mi = 0; mi < 4; mi++)
#pragma unroll
        for (int nj = 0; nj < 4; nj++) {
            int r_ = row0 + mi * 16;
            int c_ = col0 + nj * 8;
            vp[(size_t)c_ * NN + r_]           = acc[mi][nj][0];
            vp[(size_t)(c_ + 1) * NN + r_]     = acc[mi][nj][1];
            vp[(size_t)c_ * NN + r_ + 8]       = acc[mi][nj][2];
            vp[(size_t)(c_ + 1) * NN + r_ + 8] = acc[mi][nj][3];
        }
}

// ---------------------------------------------------------------------------
// CG update: one block (1024 threads) per real column, vectorized,
// shuffle-based reductions, power-of-2 column scaling.
// ---------------------------------------------------------------------------
__global__ void k_update(int it) {
    __shared__ float red[32];
    __shared__ float bc;
    const int E4 = NN / 4 / 1024;   // 2 float4 iterations

    int j = blockIdx.x;
    int tid = threadIdx.x;
    float c = g_pscale[j];
    const float4* V0 = (const float4*)(g_Vpart + (size_t)j * NN);
    const float4* V1 = (const float4*)(g_Vpart + ((size_t)MP + j) * NN);
    const float4* R4 = (const float4*)(g_R + (size_t)j * NN);
    const uint2* Ph2 = (const uint2*)(g_Ph16 + (size_t)j * NN);
    const uint2* Pl2 = (const uint2*)(g_Pl16 + (size_t)j * NN);

    float4 p[E4], v[E4], r[E4];
    float pv = 0.0f;
#pragma unroll
    for (int t = 0; t < E4; t++) {
        int i4 = t * 1024 + tid;
        float4 a = V0[i4], b = V1[i4];
        float4 s = make_float4(a.x + b.x, a.y + b.y, a.z + b.z, a.w + b.w);
        v[t] = s;
        uint2 hu = Ph2[i4], lu = Pl2[i4];
        __half2 h0 = *(__half2*)&hu.x, h1 = *(__half2*)&hu.y;
        __half2 l0 = *(__half2*)&lu.x, l1 = *(__half2*)&lu.y;
        float2 f0 = __half22float2(h0), f1 = __half22float2(h1);
        float2 g0 = __half22float2(l0), g1 = __half22float2(l1);
        float4 pp = make_float4(f0.x + g0.x, f0.y + g0.y, f1.x + g1.x, f1.y + g1.y);
        p[t] = pp;
        pv += pp.x * s.x + pp.y * s.y + pp.z * s.z + pp.w * s.w;
    }
    pv = fastReduce1024(pv, red, &bc);         // = c^2 * (P.V)
    float rs_old = g_rs[j];
    float alpha = rs_old * c * c / pv;         // true alpha
    float aoc = alpha / c;

    float rr = 0.0f;
#pragma unroll
    for (int t = 0; t < E4; t++) {
        int i4 = t * 1024 + tid;
        float4 rv = R4[i4];
        rv.x -= aoc * v[t].x; rv.y -= aoc * v[t].y;
        rv.z -= aoc * v[t].z; rv.w -= aoc * v[t].w;
        r[t] = rv;
        rr += rv.x * rv.x + rv.y * rv.y + rv.z * rv.z + rv.w * rv.w;
    }
    if (j == 0) {
        float4* X4 = (float4*)g_X;
#pragma unroll
        for (int t = 0; t < E4; t++) {
            int i4 = t * 1024 + tid;
            float4 x = X4[i4];
            x.x += aoc * p[t].x; x.y += aoc * p[t].y;
            x.z += aoc * p[t].z; x.w += aoc * p[t].w;
            X4[i4] = x;
        }
    }
    rr = fastReduce1024(rr, red, &bc);
    float beta = rr / rs_old;
    float c2 = exp2f(-rintf(0.5f * log2f(rr * (1.0f / (float)NN))));
    if (tid == 0) {
        g_rs[j] = rr;
        g_alpha[it * MP + j] = alpha;
        g_beta[it * MP + j]  = beta;
        g_pscale[j] = c2;
    }
    float boc = beta / c;

    uint2* Phw = (uint2*)(g_Ph16 + (size_t)j * NN);
    uint2* Plw = (uint2*)(g_Pl16 + (size_t)j * NN);
    float4* Rw = (float4*)(g_R + (size_t)j * NN);
#pragma unroll
    for (int t = 0; t < E4; t++) {
        int i4 = t * 1024 + tid;
        float pn[4] = {
            r[t].x + boc * p[t].x, r[t].y + boc * p[t].y,
            r[t].z + boc * p[t].z, r[t].w + boc * p[t].w };
        __half hh[4]; float ll[4];
#pragma unroll
        for (int q = 0; q < 4; q++) {
            float ps = c2 * pn[q];
            hh[q] = __float2half_rn(ps);
            ll[q] = ps - __half2float(hh[q]);
        }
        uint2 hu, lu;
        __half2 t0 = __halves2half2(hh[0], hh[1]);
        __half2 t1 = __halves2half2(hh[2], hh[3]);
        hu.x = *(uint32_t*)&t0; hu.y = *(uint32_t*)&t1;
        __half2 u0 = __floats2half2_rn(ll[0], ll[1]);
        __half2 u1 = __floats2half2_rn(ll[2], ll[3]);
        lu.x = *(uint32_t*)&u0; lu.y = *(uint32_t*)&u1;
        Phw[i4] = hu;
        Plw[i4] = lu;
        Rw[i4] = r[t];
    }
}

// ---------------------------------------------------------------------------
// SLQ logdet (TQLI on 30x30 tridiagonal, first-row eigenvector weights)
// ---------------------------------------------------------------------------
__device__ void tqli30(double* d, double* e, double* z) {
    const int n = PITER;
    for (int l = 0; l < n; l++) {
        int iter = 0;
        int m;
        do {
            for (m = l; m < n - 1; m++) {
                double dd = fabs(d[m]) + fabs(d[m + 1]);
                if (fabs(e[m]) <= 2.3e-16 * dd) break;
            }
            if (m != l) {
                if (iter++ == 64) break;
                double g = (d[l + 1] - d[l]) / (2.0 * e[l]);
                double rr = sqrt(g * g + 1.0);
                double sg = (g >= 0.0) ? rr : -rr;
                g = d[m] - d[l] + e[l] / (g + sg);
                double s = 1.0, cc = 1.0, p = 0.0;
                bool under = false;
                for (int i = m - 1; i >= l; i--) {
                    double f = s * e[i];
                    double b = cc * e[i];
                    double rq = sqrt(f * f + g * g);
                    e[i + 1] = rq;
                    if (rq == 0.0) {
                        d[i + 1] -= p;
                        e[m] = 0.0;
                        under = true;
                        break;
                    }
                    s = f / rq; cc = g / rq;
                    g = d[i + 1] - p;
                    rq = (d[i] - g) * s + 2.0 * cc * b;
                    p = s * rq;
                    d[i + 1] = g + p;
                    g = cc * rq - b;
                    double zi = z[i], zi1 = z[i + 1];
                    z[i + 1] = s * zi + cc * zi1;
                    z[i]     = cc * zi - s * zi1;
                }
                if (under) continue;
                d[l] -= p;
                e[l] = g;
                e[m] = 0.0;
            }
        } while (m != l);
    }
}

__global__ void k_logdet() {
    __shared__ double qsum[128];
    int tid = threadIdx.x;
    double quad = 0.0;
    if (tid < 100) {
        int j = tid + 1;
        double d[PITER], e[PITER], z[PITER];
        double pa = 1.0, pb = 0.0;
        for (int k = 0; k < PITER; k++) {
            double a = (double)g_alpha[k * MP + j];
            double b = (double)g_beta[k * MP + j];
            d[k] = 1.0 / a + ((k > 0) ? pb / pa : 0.0);
            e[k] = (k < PITER - 1) ? sqrt(b) / a : 0.0;
            z[k] = (k == 0) ? 1.0 : 0.0;
            pa = a; pb = b;
        }
        tqli30(d, e, z);
        for (int k = 0; k < PITER; k++) {
            double lam = d[k] < 1e-12 ? 1e-12 : d[k];
            quad += z[k] * z[k] * log(lam);
        }
    }
    qsum[tid] = quad;
    __syncthreads();
    if (tid == 0) {
        double s = 0.0;
        for (int i = 0; i < 100; i++) s += qsum[i];
        g_logdet = (float)((double)NN * s / 100.0);
    }
}

__global__ void k_final(const float* __restrict__ y, float* __restrict__ out) {
    __shared__ float red[256];
    float s = 0.0f;
    for (int i = threadIdx.x; i < NN; i += 256) s += y[i] * g_X[i];
    s = blockReduce<256>(s, red);
    if (threadIdx.x == 0) {
        const double LOG2PI = 1.8378770664093454836;
        double r = -0.5 * (double)s - 0.5 * (double)g_logdet - 0.5 * (double)NN * LOG2PI;
        out[0] = (float)r;
    }
}

// ---------------------------------------------------------------------------
// Launch
// ---------------------------------------------------------------------------
extern "C" void kernel_launch(void* const* d_in, const int* in_sizes, int n_in,
                              void* d_out, int out_size) {
    const float* K = (const float*)d_in[0];
    const float* y = (const float*)d_in[1];
    const float* Z = (const float*)d_in[2];
    float* out = (float*)d_out;

    cudaFuncSetAttribute(k_gemm_mma, cudaFuncAttributeMaxDynamicSharedMemorySize, SMEM_DYN);

    k_split<<<4096, 256>>>(K);
    k_init<<<512, 256>>>(y, Z);
    k_rsinit<<<MREAL, 256>>>();
    for (int it = 0; it < PITER; it++) {
        k_gemm_mma<<<64 * KSPLIT, 256, SMEM_DYN>>>();
        k_update<<<MREAL, 1024>>>(it);
    }
    k_logdet<<<1, 128>>>();
    k_final<<<1, 256>>>(y, out);
}

// round 6
// speedup vs baseline: 1.4069x; 1.1158x over previous
#include <cuda_runtime.h>
#include <cuda_fp16.h>
#include <math.h>
#include <stdint.h>

// ---------------------------------------------------------------------------
// Problem constants
// ---------------------------------------------------------------------------
#define NN      8192
#define MREAL   101
#define MP      128
#define PITER   30
#define KSPLIT  4
#define KCHUNK  (NN / KSPLIT)        // 2048
#define KT      64                   // k per pipeline stage
#define KITERS  (KCHUNK / KT)        // 32
#define NSTG    3
#define ROWB    256
#define A_B     (ROWB * KT * 2)      // 32768 B: A plane (256 rows x 64 k fp16)
#define B_B     (128 * KT * 2)       // 16384 B: one B plane (128 cols x 64 k)
#define STAGE_B (A_B + 2 * B_B)      // 65536 B
#define SMEM_DYN (NSTG * STAGE_B)    // 196608 B

// ---------------------------------------------------------------------------
// Scratch (static device globals; no allocation allowed)
// ---------------------------------------------------------------------------
__device__ __half g_Khi16[(size_t)NN * NN];     // 128 MB: fp16-rounded K
__device__ __half g_Ph16[(size_t)MP * NN];      // scaled P hi, col-major
__device__ __half g_Pl16[(size_t)MP * NN];      // scaled P lo
__device__ float  g_R[(size_t)MP * NN];
__device__ float  g_X[NN];
__device__ float  g_rs[MP];
__device__ float  g_pscale[MP];                 // power-of-2 column scale
__device__ float  g_Vpart[(size_t)KSPLIT * MP * NN];  // 16 MB
__device__ float  g_alpha[PITER * MP];
__device__ float  g_beta[PITER * MP];
__device__ float  g_logdet;

// ---------------------------------------------------------------------------
// PTX helpers (family-portable only: ldmatrix / mma.sync / cp.async)
// ---------------------------------------------------------------------------
__device__ __forceinline__ uint32_t smem_u32(const void* p) {
    uint32_t a;
    asm("{ .reg .u64 t; cvta.to.shared.u64 t, %1; cvt.u32.u64 %0, t; }"
        : "=r"(a) : "l"(p));
    return a;
}

__device__ __forceinline__ void ldsm_x4(uint32_t (&r)[4], uint32_t addr) {
    asm volatile("ldmatrix.sync.aligned.m8n8.x4.shared.b16 {%0,%1,%2,%3}, [%4];"
        : "=r"(r[0]), "=r"(r[1]), "=r"(r[2]), "=r"(r[3]) : "r"(addr));
}

__device__ __forceinline__ void mma16816(float (&d)[4], const uint32_t (&a)[4],
                                         uint32_t b0, uint32_t b1) {
    asm volatile("mma.sync.aligned.m16n8k16.row.col.f32.f16.f16.f32 "
        "{%0,%1,%2,%3}, {%4,%5,%6,%7}, {%8,%9}, {%0,%1,%2,%3};"
        : "+f"(d[0]), "+f"(d[1]), "+f"(d[2]), "+f"(d[3])
        : "r"(a[0]), "r"(a[1]), "r"(a[2]), "r"(a[3]), "r"(b0), "r"(b1));
}

#define CPASYNC16(dst, src) \
    asm volatile("cp.async.cg.shared.global [%0], [%1], 16;" \
                 :: "r"(dst), "l"(__cvta_generic_to_global(src)) : "memory")

// Conflict-free swizzle for 128B rows (r = row, ch = 16B chunk 0..7)
#define SWZ(r, ch) (((r) << 7) + ((((ch) ^ ((r) & 7))) << 4))

// ---------------------------------------------------------------------------
// Reductions
// ---------------------------------------------------------------------------
template <int BS>
__device__ __forceinline__ float blockReduce(float v, float* red) {
    int tid = threadIdx.x;
    red[tid] = v;
    __syncthreads();
#pragma unroll
    for (int s = BS / 2; s > 0; s >>= 1) {
        if (tid < s) red[tid] += red[tid + s];
        __syncthreads();
    }
    float out = red[0];
    __syncthreads();
    return out;
}

__device__ __forceinline__ float fastReduce1024(float v, float* red, float* bcast) {
    int lane = threadIdx.x & 31, wid = threadIdx.x >> 5;
#pragma unroll
    for (int o = 16; o > 0; o >>= 1) v += __shfl_xor_sync(0xFFFFFFFFu, v, o);
    if (lane == 0) red[wid] = v;
    __syncthreads();
    if (wid == 0) {
        float x = red[lane];
#pragma unroll
        for (int o = 16; o > 0; o >>= 1) x += __shfl_xor_sync(0xFFFFFFFFu, x, o);
        if (lane == 0) *bcast = x;
    }
    __syncthreads();
    return *bcast;
}

// ---------------------------------------------------------------------------
// Round K to fp16 (once per launch)
// ---------------------------------------------------------------------------
__global__ void k_split(const float* __restrict__ K) {
    size_t i0 = (size_t)blockIdx.x * blockDim.x + threadIdx.x;
    size_t stride = (size_t)gridDim.x * blockDim.x;
    size_t n8 = (size_t)NN * NN / 8;
    for (size_t i = i0; i < n8; i += stride) {
        float4 a = ((const float4*)K)[2 * i];
        float4 b = ((const float4*)K)[2 * i + 1];
        union { __half h[8]; uint4 u; } H;
        H.h[0] = __float2half_rn(a.x); H.h[1] = __float2half_rn(a.y);
        H.h[2] = __float2half_rn(a.z); H.h[3] = __float2half_rn(a.w);
        H.h[4] = __float2half_rn(b.x); H.h[5] = __float2half_rn(b.y);
        H.h[6] = __float2half_rn(b.z); H.h[7] = __float2half_rn(b.w);
        ((uint4*)g_Khi16)[i] = H.u;
    }
}

// ---------------------------------------------------------------------------
// Init: B = [y | Z | 0-pad]; Ph/Pl = fp16 split of B (scale 1), R = B, X = 0
// ---------------------------------------------------------------------------
__global__ void k_init(const float* __restrict__ y, const float* __restrict__ Z) {
    int stride = gridDim.x * blockDim.x;
    for (int idx = blockIdx.x * blockDim.x + threadIdx.x; idx < MP * NN; idx += stride) {
        int col = idx >> 13;
        int row = idx & (NN - 1);
        float v = 0.0f;
        if (col == 0)        v = y[row];
        else if (col <= 100) v = Z[row * 100 + (col - 1)];
        __half h = __float2half_rn(v);
        g_Ph16[idx] = h;
        g_Pl16[idx] = __float2half_rn(v - __half2float(h));
        g_R[idx] = v;
        if (col == 0) g_X[row] = 0.0f;
        if (idx < MP) g_pscale[idx] = 1.0f;
    }
}

__global__ void k_rsinit() {
    __shared__ float red[256];
    int j = blockIdx.x;
    const float* p = g_R + (size_t)j * NN;
    float s = 0.0f;
    for (int i = threadIdx.x; i < NN; i += 256) s += p[i] * p[i];
    s = blockReduce<256>(s, red);
    if (threadIdx.x == 0) g_rs[j] = s;
}

// ---------------------------------------------------------------------------
// HMMA GEMM: Vpart[ksp] = Khi[rb:rb+256, kchunk] @ (Phi + Plo)
// CTA tile 256x128, 512 threads, warp tile 64x32 (4m x 4n warps).
// 3-stage KT=64 cp.async pipeline. grid = 32 rowblocks x KSPLIT = 128 CTAs.
// ---------------------------------------------------------------------------
__device__ __forceinline__ void issue_stage(uint32_t st, int rb, int k0, int tid) {
    // A plane: 2048 16B-chunks, 4 per thread
#pragma unroll
    for (int m = 0; m < 4; m++) {
        int idx = m * 512 + tid;
        int r = idx >> 3, ch = idx & 7;
        CPASYNC16(st + SWZ(r, ch), g_Khi16 + (size_t)(rb + r) * NN + k0 + ch * 8);
    }
    // B planes: 1024 chunks each, 2 per thread
#pragma unroll
    for (int m = 0; m < 2; m++) {
        int idx = m * 512 + tid;
        int r = idx >> 3, ch = idx & 7;
        uint32_t d = st + A_B + SWZ(r, ch);
        CPASYNC16(d, g_Ph16 + (size_t)r * NN + k0 + ch * 8);
        CPASYNC16(d + B_B, g_Pl16 + (size_t)r * NN + k0 + ch * 8);
    }
    asm volatile("cp.async.commit_group;" ::: "memory");
}

__global__ void __launch_bounds__(512) k_gemm_mma() {
    extern __shared__ char smem[];
    uint32_t sb = smem_u32(smem);
    int tid = threadIdx.x, lane = tid & 31, w = tid >> 5;
    int wm = w & 3, wn = w >> 2;          // 4 m-bands x 4 n-bands
    int bid = blockIdx.x;
    int rb = (bid & 31) * ROWB;
    int ksp = bid >> 5;
    int kbase = ksp * KCHUNK;

    float acc[4][4][4];
#pragma unroll
    for (int mi = 0; mi < 4; mi++)
#pragma unroll
        for (int nj = 0; nj < 4; nj++)
#pragma unroll
            for (int q = 0; q < 4; q++) acc[mi][nj][q] = 0.0f;

    issue_stage(sb, rb, kbase, tid);
    issue_stage(sb + STAGE_B, rb, kbase + KT, tid);

    int rA = wm * 64 + (lane & 15);
    int rB = wn * 32 + (lane & 15);
    int chHalf = lane >> 4;

    uint32_t st = sb;
    for (int t = 0; t < KITERS; t++) {
        if (t < KITERS - 1) asm volatile("cp.async.wait_group 1;" ::: "memory");
        else                asm volatile("cp.async.wait_group 0;" ::: "memory");
        __syncthreads();
        if (t + 2 < KITERS) {
            uint32_t nst = st + 2 * STAGE_B;
            if (nst >= sb + NSTG * STAGE_B) nst -= NSTG * STAGE_B;
            issue_stage(nst, rb, kbase + (t + 2) * KT, tid);
        }

#pragma unroll
        for (int kk = 0; kk < 4; kk++) {
            int ch = kk * 2 + chHalf;
            uint32_t ah[4][4], bh[2][4], bl[2][4];
#pragma unroll
            for (int i = 0; i < 4; i++)
                ldsm_x4(ah[i], st + SWZ(rA + i * 16, ch));
            ldsm_x4(bh[0], st + A_B + SWZ(rB, ch));
            ldsm_x4(bh[1], st + A_B + SWZ(rB + 16, ch));
            ldsm_x4(bl[0], st + A_B + B_B + SWZ(rB, ch));
            ldsm_x4(bl[1], st + A_B + B_B + SWZ(rB + 16, ch));
#pragma unroll
            for (int mi = 0; mi < 4; mi++)
#pragma unroll
                for (int nj = 0; nj < 4; nj++) {
                    int g = nj >> 1, sel = nj & 1;
                    mma16816(acc[mi][nj], ah[mi], bh[g][sel], bh[g][sel + 2]);
                    mma16816(acc[mi][nj], ah[mi], bl[g][sel], bl[g][sel + 2]);
                }
        }
        st += STAGE_B;
        if (st >= sb + NSTG * STAGE_B) st -= NSTG * STAGE_B;
    }

    // epilogue: scatter fp32 accumulators to Vpart (col-major [col][row])
    float* vp = g_Vpart + (size_t)ksp * MP * NN;
    int row0 = rb + wm * 64 + (lane >> 2);
    int col0 = wn * 32 + (lane & 3) * 2;
#pragma unroll
    for (int mi = 0; mi < 4; mi++)
#pragma unroll
        for (int nj = 0; nj < 4; nj++) {
            int r_ = row0 + mi * 16;
            int c_ = col0 + nj * 8;
            vp[(size_t)c_ * NN + r_]           = acc[mi][nj][0];
            vp[(size_t)(c_ + 1) * NN + r_]     = acc[mi][nj][1];
            vp[(size_t)c_ * NN + r_ + 8]       = acc[mi][nj][2];
            vp[(size_t)(c_ + 1) * NN + r_ + 8] = acc[mi][nj][3];
        }
}

// ---------------------------------------------------------------------------
// CG update: one block (1024 threads) per real column, vectorized,
// shuffle-based reductions, power-of-2 column scaling.
// ---------------------------------------------------------------------------
__global__ void k_update(int it) {
    __shared__ float red[32];
    __shared__ float bc;
    const int E4 = NN / 4 / 1024;   // 2 float4 iterations

    int j = blockIdx.x;
    int tid = threadIdx.x;
    float c = g_pscale[j];
    const float4* V0 = (const float4*)(g_Vpart + (size_t)j * NN);
    const float4* V1 = (const float4*)(g_Vpart + ((size_t)MP + j) * NN);
    const float4* V2 = (const float4*)(g_Vpart + ((size_t)2 * MP + j) * NN);
    const float4* V3 = (const float4*)(g_Vpart + ((size_t)3 * MP + j) * NN);
    const float4* R4 = (const float4*)(g_R + (size_t)j * NN);
    const uint2* Ph2 = (const uint2*)(g_Ph16 + (size_t)j * NN);
    const uint2* Pl2 = (const uint2*)(g_Pl16 + (size_t)j * NN);

    float4 p[E4], v[E4], r[E4];
    float pv = 0.0f;
#pragma unroll
    for (int t = 0; t < E4; t++) {
        int i4 = t * 1024 + tid;
        float4 a = V0[i4], b = V1[i4], d2 = V2[i4], e2 = V3[i4];
        float4 s = make_float4(a.x + b.x + d2.x + e2.x, a.y + b.y + d2.y + e2.y,
                               a.z + b.z + d2.z + e2.z, a.w + b.w + d2.w + e2.w);
        v[t] = s;
        uint2 hu = Ph2[i4], lu = Pl2[i4];
        __half2 h0 = *(__half2*)&hu.x, h1 = *(__half2*)&hu.y;
        __half2 l0 = *(__half2*)&lu.x, l1 = *(__half2*)&lu.y;
        float2 f0 = __half22float2(h0), f1 = __half22float2(h1);
        float2 g0 = __half22float2(l0), g1 = __half22float2(l1);
        float4 pp = make_float4(f0.x + g0.x, f0.y + g0.y, f1.x + g1.x, f1.y + g1.y);
        p[t] = pp;
        pv += pp.x * s.x + pp.y * s.y + pp.z * s.z + pp.w * s.w;
    }
    pv = fastReduce1024(pv, red, &bc);         // = c^2 * (P.V)
    float rs_old = g_rs[j];
    float alpha = rs_old * c * c / pv;         // true alpha
    float aoc = alpha / c;

    float rr = 0.0f;
#pragma unroll
    for (int t = 0; t < E4; t++) {
        int i4 = t * 1024 + tid;
        float4 rv = R4[i4];
        rv.x -= aoc * v[t].x; rv.y -= aoc * v[t].y;
        rv.z -= aoc * v[t].z; rv.w -= aoc * v[t].w;
        r[t] = rv;
        rr += rv.x * rv.x + rv.y * rv.y + rv.z * rv.z + rv.w * rv.w;
    }
    if (j == 0) {
        float4* X4 = (float4*)g_X;
#pragma unroll
        for (int t = 0; t < E4; t++) {
            int i4 = t * 1024 + tid;
            float4 x = X4[i4];
            x.x += aoc * p[t].x; x.y += aoc * p[t].y;
            x.z += aoc * p[t].z; x.w += aoc * p[t].w;
            X4[i4] = x;
        }
    }
    rr = fastReduce1024(rr, red, &bc);
    float beta = rr / rs_old;
    float c2 = exp2f(-rintf(0.5f * log2f(rr * (1.0f / (float)NN))));
    if (tid == 0) {
        g_rs[j] = rr;
        g_alpha[it * MP + j] = alpha;
        g_beta[it * MP + j]  = beta;
        g_pscale[j] = c2;
    }
    float boc = beta / c;

    uint2* Phw = (uint2*)(g_Ph16 + (size_t)j * NN);
    uint2* Plw = (uint2*)(g_Pl16 + (size_t)j * NN);
    float4* Rw = (float4*)(g_R + (size_t)j * NN);
#pragma unroll
    for (int t = 0; t < E4; t++) {
        int i4 = t * 1024 + tid;
        float pn[4] = {
            r[t].x + boc * p[t].x, r[t].y + boc * p[t].y,
            r[t].z + boc * p[t].z, r[t].w + boc * p[t].w };
        __half hh[4]; float ll[4];
#pragma unroll
        for (int q = 0; q < 4; q++) {
            float ps = c2 * pn[q];
            hh[q] = __float2half_rn(ps);
            ll[q] = ps - __half2float(hh[q]);
        }
        uint2 hu, lu;
        __half2 t0 = __halves2half2(hh[0], hh[1]);
        __half2 t1 = __halves2half2(hh[2], hh[3]);
        hu.x = *(uint32_t*)&t0; hu.y = *(uint32_t*)&t1;
        __half2 u0 = __floats2half2_rn(ll[0], ll[1]);
        __half2 u1 = __floats2half2_rn(ll[2], ll[3]);
        lu.x = *(uint32_t*)&u0; lu.y = *(uint32_t*)&u1;
        Phw[i4] = hu;
        Plw[i4] = lu;
        Rw[i4] = r[t];
    }
}

// ---------------------------------------------------------------------------
// SLQ logdet (TQLI on 30x30 tridiagonal, first-row eigenvector weights)
// ---------------------------------------------------------------------------
__device__ void tqli30(double* d, double* e, double* z) {
    const int n = PITER;
    for (int l = 0; l < n; l++) {
        int iter = 0;
        int m;
        do {
            for (m = l; m < n - 1; m++) {
                double dd = fabs(d[m]) + fabs(d[m + 1]);
                if (fabs(e[m]) <= 2.3e-16 * dd) break;
            }
            if (m != l) {
                if (iter++ == 64) break;
                double g = (d[l + 1] - d[l]) / (2.0 * e[l]);
                double rr = sqrt(g * g + 1.0);
                double sg = (g >= 0.0) ? rr : -rr;
                g = d[m] - d[l] + e[l] / (g + sg);
                double s = 1.0, cc = 1.0, p = 0.0;
                bool under = false;
                for (int i = m - 1; i >= l; i--) {
                    double f = s * e[i];
                    double b = cc * e[i];
                    double rq = sqrt(f * f + g * g);
                    e[i + 1] = rq;
                    if (rq == 0.0) {
                        d[i + 1] -= p;
                        e[m] = 0.0;
                        under = true;
                        break;
                    }
                    s = f / rq; cc = g / rq;
                    g = d[i + 1] - p;
                    rq = (d[i] - g) * s + 2.0 * cc * b;
                    p = s * rq;
                    d[i + 1] = g + p;
                    g = cc * rq - b;
                    double zi = z[i], zi1 = z[i + 1];
                    z[i + 1] = s * zi + cc * zi1;
                    z[i]     = cc * zi - s * zi1;
                }
                if (under) continue;
                d[l] -= p;
                e[l] = g;
                e[m] = 0.0;
            }
        } while (m != l);
    }
}

__global__ void k_logdet() {
    __shared__ double qsum[128];
    int tid = threadIdx.x;
    double quad = 0.0;
    if (tid < 100) {
        int j = tid + 1;
        double d[PITER], e[PITER], z[PITER];
        double pa = 1.0, pb = 0.0;
        for (int k = 0; k < PITER; k++) {
            double a = (double)g_alpha[k * MP + j];
            double b = (double)g_beta[k * MP + j];
            d[k] = 1.0 / a + ((k > 0) ? pb / pa : 0.0);
            e[k] = (k < PITER - 1) ? sqrt(b) / a : 0.0;
            z[k] = (k == 0) ? 1.0 : 0.0;
            pa = a; pb = b;
        }
        tqli30(d, e, z);
        for (int k = 0; k < PITER; k++) {
            double lam = d[k] < 1e-12 ? 1e-12 : d[k];
            quad += z[k] * z[k] * log(lam);
        }
    }
    qsum[tid] = quad;
    __syncthreads();
    if (tid == 0) {
        double s = 0.0;
        for (int i = 0; i < 100; i++) s += qsum[i];
        g_logdet = (float)((double)NN * s / 100.0);
    }
}

__global__ void k_final(const float* __restrict__ y, float* __restrict__ out) {
    __shared__ float red[256];
    float s = 0.0f;
    for (int i = threadIdx.x; i < NN; i += 256) s += y[i] * g_X[i];
    s = blockReduce<256>(s, red);
    if (threadIdx.x == 0) {
        const double LOG2PI = 1.8378770664093454836;
        double r = -0.5 * (double)s - 0.5 * (double)g_logdet - 0.5 * (double)NN * LOG2PI;
        out[0] = (float)r;
    }
}

// ---------------------------------------------------------------------------
// Launch
// ---------------------------------------------------------------------------
extern "C" void kernel_launch(void* const* d_in, const int* in_sizes, int n_in,
                              void* d_out, int out_size) {
    const float* K = (const float*)d_in[0];
    const float* y = (const float*)d_in[1];
    const float* Z = (const float*)d_in[2];
    float* out = (float*)d_out;

    cudaFuncSetAttribute(k_gemm_mma, cudaFuncAttributeMaxDynamicSharedMemorySize, SMEM_DYN);

    k_split<<<4096, 256>>>(K);
    k_init<<<512, 256>>>(y, Z);
    k_rsinit<<<MREAL, 256>>>();
    for (int it = 0; it < PITER; it++) {
        k_gemm_mma<<<32 * KSPLIT, 512, SMEM_DYN>>>();
        k_update<<<MREAL, 1024>>>(it);
    }
    k_logdet<<<1, 128>>>();
    k_final<<<1, 256>>>(y, out);
}

// round 7
// speedup vs baseline: 1.4097x; 1.0020x over previous
#include <cuda_runtime.h>
#include <cuda_fp16.h>
#include <math.h>
#include <stdint.h>

// ---------------------------------------------------------------------------
// Problem constants
// ---------------------------------------------------------------------------
#define NN      8192
#define MREAL   101
#define MP      128
#define PITER   30
#define KSPLIT  4
#define KCHUNK  (NN / KSPLIT)        // 2048
#define KT      64                   // k per pipeline stage
#define KITERS  (KCHUNK / KT)        // 32
#define NSTG    3
#define ROWB    256
#define NCTA    128                  // 32 rowblocks x KSPLIT, 1 CTA/SM
#define A_B     (ROWB * KT * 2)      // 32768 B: A plane (256 rows x 64 k fp16)
#define B_B     (128 * KT * 2)       // 16384 B: one B plane (128 cols x 64 k)
#define STAGE_B (A_B + 2 * B_B)      // 65536 B
#define SMEM_DYN (NSTG * STAGE_B)    // 196608 B

// ---------------------------------------------------------------------------
// Scratch (static device globals; no allocation allowed)
// ---------------------------------------------------------------------------
__device__ __half g_Khi16[(size_t)NN * NN];     // 128 MB: fp16-rounded K
__device__ __half g_Ph16[(size_t)MP * NN];      // scaled P hi, col-major
__device__ __half g_Pl16[(size_t)MP * NN];      // scaled P lo
__device__ float  g_R[(size_t)MP * NN];
__device__ float  g_X[NN];
__device__ float  g_Vpart[(size_t)KSPLIT * MP * NN];  // 16 MB
__device__ float  g_alpha[PITER * MP];
__device__ float  g_beta[PITER * MP];
__device__ float  g_logdet;

// grid barrier state (self-resetting; g_gen monotonic across graph replays)
__device__ unsigned g_cnt = 0;
__device__ volatile unsigned g_gen = 0;

// ---------------------------------------------------------------------------
// PTX helpers (family-portable only: ldmatrix / mma.sync / cp.async)
// ---------------------------------------------------------------------------
__device__ __forceinline__ uint32_t smem_u32(const void* p) {
    uint32_t a;
    asm("{ .reg .u64 t; cvta.to.shared.u64 t, %1; cvt.u32.u64 %0, t; }"
        : "=r"(a) : "l"(p));
    return a;
}

__device__ __forceinline__ void ldsm_x4(uint32_t (&r)[4], uint32_t addr) {
    asm volatile("ldmatrix.sync.aligned.m8n8.x4.shared.b16 {%0,%1,%2,%3}, [%4];"
        : "=r"(r[0]), "=r"(r[1]), "=r"(r[2]), "=r"(r[3]) : "r"(addr));
}

__device__ __forceinline__ void mma16816(float (&d)[4], const uint32_t (&a)[4],
                                         uint32_t b0, uint32_t b1) {
    asm volatile("mma.sync.aligned.m16n8k16.row.col.f32.f16.f16.f32 "
        "{%0,%1,%2,%3}, {%4,%5,%6,%7}, {%8,%9}, {%0,%1,%2,%3};"
        : "+f"(d[0]), "+f"(d[1]), "+f"(d[2]), "+f"(d[3])
        : "r"(a[0]), "r"(a[1]), "r"(a[2]), "r"(a[3]), "r"(b0), "r"(b1));
}

#define CPASYNC16(dst, src) \
    asm volatile("cp.async.cg.shared.global [%0], [%1], 16;" \
                 :: "r"(dst), "l"(__cvta_generic_to_global(src)) : "memory")

// Conflict-free swizzle for 128B rows (r = row, ch = 16B chunk 0..7)
#define SWZ(r, ch) (((r) << 7) + ((((ch) ^ ((r) & 7))) << 4))

// ---------------------------------------------------------------------------
// Reductions
// ---------------------------------------------------------------------------
template <int BS>
__device__ __forceinline__ float blockReduce(float v, float* red) {
    int tid = threadIdx.x;
    red[tid] = v;
    __syncthreads();
#pragma unroll
    for (int s = BS / 2; s > 0; s >>= 1) {
        if (tid < s) red[tid] += red[tid + s];
        __syncthreads();
    }
    float out = red[0];
    __syncthreads();
    return out;
}

__device__ __forceinline__ float fastReduce512(float v, volatile float* red,
                                               volatile float* bc) {
    int lane = threadIdx.x & 31, wid = threadIdx.x >> 5;
#pragma unroll
    for (int o = 16; o > 0; o >>= 1) v += __shfl_xor_sync(0xFFFFFFFFu, v, o);
    if (lane == 0) red[wid] = v;
    __syncthreads();
    if (wid == 0) {
        float x = (lane < 16) ? red[lane] : 0.0f;
#pragma unroll
        for (int o = 8; o > 0; o >>= 1) x += __shfl_xor_sync(0xFFFFFFFFu, x, o);
        if (lane == 0) *bc = x;
    }
    __syncthreads();
    return *bc;
}

// ---------------------------------------------------------------------------
// Grid barrier: sense-reversing, self-resetting counter + monotonic gen flag.
// ---------------------------------------------------------------------------
__device__ __forceinline__ void gridSync(unsigned& gen) {
    __syncthreads();
    if (threadIdx.x == 0) {
        __threadfence();
        unsigned target = gen + 1;
        unsigned old = atomicAdd(&g_cnt, 1);
        if (old == NCTA - 1) {
            g_cnt = 0;
            __threadfence();
            g_gen = target;
        } else {
            while (g_gen != target) { __nanosleep(32); }
        }
        __threadfence();
        gen = target;
    }
    __syncthreads();
}

// ---------------------------------------------------------------------------
// Round K to fp16 (once per launch)
// ---------------------------------------------------------------------------
__global__ void k_split(const float* __restrict__ K) {
    size_t i0 = (size_t)blockIdx.x * blockDim.x + threadIdx.x;
    size_t stride = (size_t)gridDim.x * blockDim.x;
    size_t n8 = (size_t)NN * NN / 8;
    for (size_t i = i0; i < n8; i += stride) {
        float4 a = ((const float4*)K)[2 * i];
        float4 b = ((const float4*)K)[2 * i + 1];
        union { __half h[8]; uint4 u; } H;
        H.h[0] = __float2half_rn(a.x); H.h[1] = __float2half_rn(a.y);
        H.h[2] = __float2half_rn(a.z); H.h[3] = __float2half_rn(a.w);
        H.h[4] = __float2half_rn(b.x); H.h[5] = __float2half_rn(b.y);
        H.h[6] = __float2half_rn(b.z); H.h[7] = __float2half_rn(b.w);
        ((uint4*)g_Khi16)[i] = H.u;
    }
}

// ---------------------------------------------------------------------------
// Init: B = [y | Z | 0-pad]; Ph/Pl = fp16 split of B (scale 1), R = B, X = 0
// ---------------------------------------------------------------------------
__global__ void k_init(const float* __restrict__ y, const float* __restrict__ Z) {
    int stride = gridDim.x * blockDim.x;
    for (int idx = blockIdx.x * blockDim.x + threadIdx.x; idx < MP * NN; idx += stride) {
        int col = idx >> 13;
        int row = idx & (NN - 1);
        float v = 0.0f;
        if (col == 0)        v = y[row];
        else if (col <= 100) v = Z[row * 100 + (col - 1)];
        __half h = __float2half_rn(v);
        g_Ph16[idx] = h;
        g_Pl16[idx] = __float2half_rn(v - __half2float(h));
        g_R[idx] = v;
        if (col == 0) g_X[row] = 0.0f;
    }
}

// ---------------------------------------------------------------------------
// cp.async stage fill for the GEMM phase
// ---------------------------------------------------------------------------
__device__ __forceinline__ void issue_stage(uint32_t st, int rb, int k0, int tid) {
#pragma unroll
    for (int m = 0; m < 4; m++) {
        int idx = m * 512 + tid;
        int r = idx >> 3, ch = idx & 7;
        CPASYNC16(st + SWZ(r, ch), g_Khi16 + (size_t)(rb + r) * NN + k0 + ch * 8);
    }
#pragma unroll
    for (int m = 0; m < 2; m++) {
        int idx = m * 512 + tid;
        int r = idx >> 3, ch = idx & 7;
        uint32_t d = st + A_B + SWZ(r, ch);
        CPASYNC16(d, g_Ph16 + (size_t)r * NN + k0 + ch * 8);
        CPASYNC16(d + B_B, g_Pl16 + (size_t)r * NN + k0 + ch * 8);
    }
    asm volatile("cp.async.commit_group;" ::: "memory");
}

// ---------------------------------------------------------------------------
// Persistent kernel: 30 x (GEMM phase -> gridSync -> update phase -> gridSync)
// 128 CTAs x 512 threads, all co-resident (1/SM).
// ---------------------------------------------------------------------------
__global__ void __launch_bounds__(512) k_persist() {
    extern __shared__ char smem[];
    uint32_t sb = smem_u32(smem);
    volatile float* red = (volatile float*)smem;       // 16 floats (phase B only)
    volatile float* bcp = (volatile float*)(smem + 64);

    int tid = threadIdx.x, lane = tid & 31, w = tid >> 5;
    int wm = w & 3, wn = w >> 2;
    int bid = blockIdx.x;
    int rb = (bid & 31) * ROWB;
    int ksp = bid >> 5;
    int kbase = ksp * KCHUNK;

    unsigned gen = g_gen;   // safe: every CTA reads before any barrier completes

    int rA = wm * 64 + (lane & 15);
    int rB = wn * 32 + (lane & 15);
    int chHalf = lane >> 4;

    // per-column CG state in registers (uniform across the CTA)
    float rs = 0.0f, csc = 1.0f;
    if (bid < MREAL) {
        const float4* R4 = (const float4*)(g_R + (size_t)bid * NN);
        float s = 0.0f;
#pragma unroll
        for (int t = 0; t < 4; t++) {
            float4 rv = R4[t * 512 + tid];
            s += rv.x * rv.x + rv.y * rv.y + rv.z * rv.z + rv.w * rv.w;
        }
        rs = fastReduce512(s, red, bcp);
    }
    __syncthreads();

    for (int it = 0; it < PITER; it++) {
        // ------------------------------ GEMM phase ------------------------
        float acc[4][4][4];
#pragma unroll
        for (int mi = 0; mi < 4; mi++)
#pragma unroll
            for (int nj = 0; nj < 4; nj++)
#pragma unroll
                for (int q = 0; q < 4; q++) acc[mi][nj][q] = 0.0f;

        issue_stage(sb, rb, kbase, tid);
        issue_stage(sb + STAGE_B, rb, kbase + KT, tid);

        uint32_t st = sb;
        for (int t = 0; t < KITERS; t++) {
            if (t < KITERS - 1) asm volatile("cp.async.wait_group 1;" ::: "memory");
            else                asm volatile("cp.async.wait_group 0;" ::: "memory");
            __syncthreads();
            if (t + 2 < KITERS) {
                uint32_t nst = st + 2 * STAGE_B;
                if (nst >= sb + NSTG * STAGE_B) nst -= NSTG * STAGE_B;
                issue_stage(nst, rb, kbase + (t + 2) * KT, tid);
            }
#pragma unroll
            for (int kk = 0; kk < 4; kk++) {
                int ch = kk * 2 + chHalf;
                uint32_t ah[4][4], bh[2][4], bl[2][4];
#pragma unroll
                for (int i = 0; i < 4; i++)
                    ldsm_x4(ah[i], st + SWZ(rA + i * 16, ch));
                ldsm_x4(bh[0], st + A_B + SWZ(rB, ch));
                ldsm_x4(bh[1], st + A_B + SWZ(rB + 16, ch));
                ldsm_x4(bl[0], st + A_B + B_B + SWZ(rB, ch));
                ldsm_x4(bl[1], st + A_B + B_B + SWZ(rB + 16, ch));
#pragma unroll
                for (int mi = 0; mi < 4; mi++)
#pragma unroll
                    for (int nj = 0; nj < 4; nj++) {
                        int g = nj >> 1, sel = nj & 1;
                        mma16816(acc[mi][nj], ah[mi], bh[g][sel], bh[g][sel + 2]);
                        mma16816(acc[mi][nj], ah[mi], bl[g][sel], bl[g][sel + 2]);
                    }
            }
            st += STAGE_B;
            if (st >= sb + NSTG * STAGE_B) st -= NSTG * STAGE_B;
        }

        {   // epilogue: scatter accumulators to Vpart (col-major [col][row])
            float* vp = g_Vpart + (size_t)ksp * MP * NN;
            int row0 = rb + wm * 64 + (lane >> 2);
            int col0 = wn * 32 + (lane & 3) * 2;
#pragma unroll
            for (int mi = 0; mi < 4; mi++)
#pragma unroll
                for (int nj = 0; nj < 4; nj++) {
                    int r_ = row0 + mi * 16;
                    int c_ = col0 + nj * 8;
                    vp[(size_t)c_ * NN + r_]           = acc[mi][nj][0];
                    vp[(size_t)(c_ + 1) * NN + r_]     = acc[mi][nj][1];
                    vp[(size_t)c_ * NN + r_ + 8]       = acc[mi][nj][2];
                    vp[(size_t)(c_ + 1) * NN + r_ + 8] = acc[mi][nj][3];
                }
        }

        gridSync(gen);   // Vpart complete before update reads it

        // ------------------------------ update phase ----------------------
        if (bid < MREAL) {
            int j = bid;
            const float4* V0 = (const float4*)g_Vpart + (size_t)j * NN / 4;
            const size_t PL = (size_t)MP * NN / 4;
            const float4* R4 = (const float4*)(g_R + (size_t)j * NN);
            const uint2* Ph2 = (const uint2*)(g_Ph16 + (size_t)j * NN);
            const uint2* Pl2 = (const uint2*)(g_Pl16 + (size_t)j * NN);

            float4 p[4], v[4], r[4];
            float pv = 0.0f;
#pragma unroll
            for (int t = 0; t < 4; t++) {
                int i4 = t * 512 + tid;
                float4 a = __ldcg(V0 + i4);
                float4 b = __ldcg(V0 + PL + i4);
                float4 d2 = __ldcg(V0 + 2 * PL + i4);
                float4 e2 = __ldcg(V0 + 3 * PL + i4);
                float4 s = make_float4(a.x + b.x + d2.x + e2.x,
                                       a.y + b.y + d2.y + e2.y,
                                       a.z + b.z + d2.z + e2.z,
                                       a.w + b.w + d2.w + e2.w);
                v[t] = s;
                uint2 hu = Ph2[i4], lu = Pl2[i4];
                __half2 h0 = *(__half2*)&hu.x, h1 = *(__half2*)&hu.y;
                __half2 l0 = *(__half2*)&lu.x, l1 = *(__half2*)&lu.y;
                float2 f0 = __half22float2(h0), f1 = __half22float2(h1);
                float2 g0 = __half22float2(l0), g1 = __half22float2(l1);
                float4 pp = make_float4(f0.x + g0.x, f0.y + g0.y,
                                        f1.x + g1.x, f1.y + g1.y);
                p[t] = pp;
                pv += pp.x * s.x + pp.y * s.y + pp.z * s.z + pp.w * s.w;
            }
            pv = fastReduce512(pv, red, bcp);      // = c^2 * (P.V)
            float alpha = rs * csc * csc / pv;
            float aoc = alpha / csc;

            float rr = 0.0f;
#pragma unroll
            for (int t = 0; t < 4; t++) {
                int i4 = t * 512 + tid;
                float4 rv = R4[i4];
                rv.x -= aoc * v[t].x; rv.y -= aoc * v[t].y;
                rv.z -= aoc * v[t].z; rv.w -= aoc * v[t].w;
                r[t] = rv;
                rr += rv.x * rv.x + rv.y * rv.y + rv.z * rv.z + rv.w * rv.w;
            }
            if (j == 0) {
                float4* X4 = (float4*)g_X;
#pragma unroll
                for (int t = 0; t < 4; t++) {
                    int i4 = t * 512 + tid;
                    float4 x = X4[i4];
                    x.x += aoc * p[t].x; x.y += aoc * p[t].y;
                    x.z += aoc * p[t].z; x.w += aoc * p[t].w;
                    X4[i4] = x;
                }
            }
            rr = fastReduce512(rr, red, bcp);
            float beta = rr / rs;
            float c2 = exp2f(-rintf(0.5f * log2f(rr * (1.0f / (float)NN))));
            if (tid == 0) {
                g_alpha[it * MP + j] = alpha;
                g_beta[it * MP + j]  = beta;
            }
            float boc = beta / csc;

            uint2* Phw = (uint2*)(g_Ph16 + (size_t)j * NN);
            uint2* Plw = (uint2*)(g_Pl16 + (size_t)j * NN);
            float4* Rw = (float4*)(g_R + (size_t)j * NN);
#pragma unroll
            for (int t = 0; t < 4; t++) {
                int i4 = t * 512 + tid;
                float pn[4] = {
                    r[t].x + boc * p[t].x, r[t].y + boc * p[t].y,
                    r[t].z + boc * p[t].z, r[t].w + boc * p[t].w };
                __half hh[4]; float ll[4];
#pragma unroll
                for (int q = 0; q < 4; q++) {
                    float ps = c2 * pn[q];
                    hh[q] = __float2half_rn(ps);
                    ll[q] = ps - __half2float(hh[q]);
                }
                uint2 hu, lu;
                __half2 t0 = __halves2half2(hh[0], hh[1]);
                __half2 t1 = __halves2half2(hh[2], hh[3]);
                hu.x = *(uint32_t*)&t0; hu.y = *(uint32_t*)&t1;
                __half2 u0 = __floats2half2_rn(ll[0], ll[1]);
                __half2 u1 = __floats2half2_rn(ll[2], ll[3]);
                lu.x = *(uint32_t*)&u0; lu.y = *(uint32_t*)&u1;
                Phw[i4] = hu;
                Plw[i4] = lu;
                Rw[i4] = r[t];
            }
            rs = rr;
            csc = c2;
        }

        gridSync(gen);   // P complete before next GEMM reads it / Vpart reuse
    }
}

// ---------------------------------------------------------------------------
// SLQ logdet (TQLI on 30x30 tridiagonal, first-row eigenvector weights)
// ---------------------------------------------------------------------------
__device__ void tqli30(double* d, double* e, double* z) {
    const int n = PITER;
    for (int l = 0; l < n; l++) {
        int iter = 0;
        int m;
        do {
            for (m = l; m < n - 1; m++) {
                double dd = fabs(d[m]) + fabs(d[m + 1]);
                if (fabs(e[m]) <= 2.3e-16 * dd) break;
            }
            if (m != l) {
                if (iter++ == 64) break;
                double g = (d[l + 1] - d[l]) / (2.0 * e[l]);
                double rr = sqrt(g * g + 1.0);
                double sg = (g >= 0.0) ? rr : -rr;
                g = d[m] - d[l] + e[l] / (g + sg);
                double s = 1.0, cc = 1.0, p = 0.0;
                bool under = false;
                for (int i = m - 1; i >= l; i--) {
                    double f = s * e[i];
                    double b = cc * e[i];
                    double rq = sqrt(f * f + g * g);
                    e[i + 1] = rq;
                    if (rq == 0.0) {
                        d[i + 1] -= p;
                        e[m] = 0.0;
                        under = true;
                        break;
                    }
                    s = f / rq; cc = g / rq;
                    g = d[i + 1] - p;
                    rq = (d[i] - g) * s + 2.0 * cc * b;
                    p = s * rq;
                    d[i + 1] = g + p;
                    g = cc * rq - b;
                    double zi = z[i], zi1 = z[i + 1];
                    z[i + 1] = s * zi + cc * zi1;
                    z[i]     = cc * zi - s * zi1;
                }
                if (under) continue;
                d[l] -= p;
                e[l] = g;
                e[m] = 0.0;
            }
        } while (m != l);
    }
}

__global__ void k_logdet() {
    __shared__ double qsum[128];
    int tid = threadIdx.x;
    double quad = 0.0;
    if (tid < 100) {
        int j = tid + 1;
        double d[PITER], e[PITER], z[PITER];
        double pa = 1.0, pb = 0.0;
        for (int k = 0; k < PITER; k++) {
            double a = (double)g_alpha[k * MP + j];
            double b = (double)g_beta[k * MP + j];
            d[k] = 1.0 / a + ((k > 0) ? pb / pa : 0.0);
            e[k] = (k < PITER - 1) ? sqrt(b) / a : 0.0;
            z[k] = (k == 0) ? 1.0 : 0.0;
            pa = a; pb = b;
        }
        tqli30(d, e, z);
        for (int k = 0; k < PITER; k++) {
            double lam = d[k] < 1e-12 ? 1e-12 : d[k];
            quad += z[k] * z[k] * log(lam);
        }
    }
    qsum[tid] = quad;
    __syncthreads();
    if (tid == 0) {
        double s = 0.0;
        for (int i = 0; i < 100; i++) s += qsum[i];
        g_logdet = (float)((double)NN * s / 100.0);
    }
}

__global__ void k_final(const float* __restrict__ y, float* __restrict__ out) {
    __shared__ float red[256];
    float s = 0.0f;
    for (int i = threadIdx.x; i < NN; i += 256) s += y[i] * g_X[i];
    s = blockReduce<256>(s, red);
    if (threadIdx.x == 0) {
        const double LOG2PI = 1.8378770664093454836;
        double r = -0.5 * (double)s - 0.5 * (double)g_logdet - 0.5 * (double)NN * LOG2PI;
        out[0] = (float)r;
    }
}

// ---------------------------------------------------------------------------
// Launch
// ---------------------------------------------------------------------------
extern "C" void kernel_launch(void* const* d_in, const int* in_sizes, int n_in,
                              void* d_out, int out_size) {
    const float* K = (const float*)d_in[0];
    const float* y = (const float*)d_in[1];
    const float* Z = (const float*)d_in[2];
    float* out = (float*)d_out;

    cudaFuncSetAttribute(k_persist, cudaFuncAttributeMaxDynamicSharedMemorySize, SMEM_DYN);

    k_split<<<4096, 256>>>(K);
    k_init<<<512, 256>>>(y, Z);
    k_persist<<<NCTA, 512, SMEM_DYN>>>();
    k_logdet<<<1, 128>>>();
    k_final<<<1, 256>>>(y, out);
}

// round 8
// speedup vs baseline: 1.4982x; 1.0627x over previous
#include <cuda.h>
#include <cuda_runtime.h>
#include <cuda_fp16.h>
#include <math.h>
#include <stdint.h>

// ---------------------------------------------------------------------------
// Problem constants
// ---------------------------------------------------------------------------
#define NN      8192
#define MREAL   101
#define MP      128
#define PITER   30
#define KSPLIT  4
#define KCHUNK  (NN / KSPLIT)        // 2048
#define KT      64                   // k per pipeline stage
#define KITERS  (KCHUNK / KT)        // 32
#define NSTG    3
#define ROWB    256
#define NCTA    128                  // 32 rowblocks x KSPLIT, 1 CTA/SM
#define A_B     (ROWB * KT * 2)      // 32768 B: A tile (256 rows x 64 k fp16)
#define B_B     (128 * KT * 2)       // 16384 B: one B tile (128 cols x 64 k)
#define STAGE_B (A_B + 2 * B_B)      // 65536 B
#define SMEM_DYN (1024 + NSTG * STAGE_B)   // 197632 B (1 KB for mbarriers)

// ---------------------------------------------------------------------------
// Scratch (static device globals; no allocation allowed)
// ---------------------------------------------------------------------------
__device__ __half g_Khi16[(size_t)NN * NN];     // 128 MB: fp16-rounded K
__device__ __half g_Ph16[(size_t)MP * NN];      // scaled P hi, col-major
__device__ __half g_Pl16[(size_t)MP * NN];      // scaled P lo
__device__ float  g_R[(size_t)MP * NN];
__device__ float  g_X[NN];
__device__ float  g_Vpart[(size_t)KSPLIT * MP * NN];  // 16 MB
__device__ float  g_alpha[PITER * MP];
__device__ float  g_beta[PITER * MP];
__device__ float  g_logdet;

// grid barrier state (self-resetting; g_gen monotonic across graph replays)
__device__ unsigned g_cnt = 0;
__device__ volatile unsigned g_gen = 0;

// ---------------------------------------------------------------------------
// PTX helpers (family-portable: ldmatrix / mma.sync / TMA / mbarrier)
// ---------------------------------------------------------------------------
__device__ __forceinline__ uint32_t smem_u32(const void* p) {
    uint32_t a;
    asm("{ .reg .u64 t; cvta.to.shared.u64 t, %1; cvt.u32.u64 %0, t; }"
        : "=r"(a) : "l"(p));
    return a;
}

__device__ __forceinline__ void ldsm_x4(uint32_t (&r)[4], uint32_t addr) {
    asm volatile("ldmatrix.sync.aligned.m8n8.x4.shared.b16 {%0,%1,%2,%3}, [%4];"
        : "=r"(r[0]), "=r"(r[1]), "=r"(r[2]), "=r"(r[3]) : "r"(addr));
}

__device__ __forceinline__ void mma16816(float (&d)[4], const uint32_t (&a)[4],
                                         uint32_t b0, uint32_t b1) {
    asm volatile("mma.sync.aligned.m16n8k16.row.col.f32.f16.f16.f32 "
        "{%0,%1,%2,%3}, {%4,%5,%6,%7}, {%8,%9}, {%0,%1,%2,%3};"
        : "+f"(d[0]), "+f"(d[1]), "+f"(d[2]), "+f"(d[3])
        : "r"(a[0]), "r"(a[1]), "r"(a[2]), "r"(a[3]), "r"(b0), "r"(b1));
}

#define MBAR_INIT(addr, cnt) \
    asm volatile("mbarrier.init.shared.b64 [%0], %1;" :: "r"(addr), "r"(cnt) : "memory")
#define MBAR_ARRIVE(addr) \
    asm volatile("mbarrier.arrive.shared.b64 _, [%0];" :: "r"(addr) : "memory")
#define MBAR_EXPECT_TX(addr, bytes) \
    asm volatile("mbarrier.arrive.expect_tx.shared.b64 _, [%0], %1;" \
                 :: "r"(addr), "r"(bytes) : "memory")

__device__ __forceinline__ void mbar_wait(uint32_t addr, uint32_t parity) {
    asm volatile(
        "{\n\t.reg .pred p;\n\t"
        "WAIT_%=:\n\t"
        "mbarrier.try_wait.parity.shared.b64 p, [%0], %1;\n\t"
        "@!p bra WAIT_%=;\n\t}"
        :: "r"(addr), "r"(parity) : "memory");
}

#define TMA2D(smem, map, x, y, mbar) \
    asm volatile("cp.async.bulk.tensor.2d.shared::cta.global.tile.mbarrier::complete_tx::bytes " \
                 "[%0], [%1, {%2, %3}], [%4];" \
                 :: "r"(smem), "l"(map), "r"(x), "r"(y), "r"(mbar) : "memory")

#define FENCE_ASYNC() asm volatile("fence.proxy.async.shared::cta;" ::: "memory")

// Swizzle matching CU_TENSOR_MAP_SWIZZLE_128B with 128B rows
// (r = row, ch = 16B chunk 0..7): byte_off ^ ((byte_off>>3)&0x70)
#define SWZ(r, ch) (((r) << 7) + ((((ch) ^ ((r) & 7))) << 4))

// ---------------------------------------------------------------------------
// Reductions
// ---------------------------------------------------------------------------
template <int BS>
__device__ __forceinline__ float blockReduce(float v, float* red) {
    int tid = threadIdx.x;
    red[tid] = v;
    __syncthreads();
#pragma unroll
    for (int s = BS / 2; s > 0; s >>= 1) {
        if (tid < s) red[tid] += red[tid + s];
        __syncthreads();
    }
    float out = red[0];
    __syncthreads();
    return out;
}

__device__ __forceinline__ float fastReduce512(float v, volatile float* red,
                                               volatile float* bc) {
    int lane = threadIdx.x & 31, wid = threadIdx.x >> 5;
#pragma unroll
    for (int o = 16; o > 0; o >>= 1) v += __shfl_xor_sync(0xFFFFFFFFu, v, o);
    if (lane == 0) red[wid] = v;
    __syncthreads();
    if (wid == 0) {
        float x = (lane < 16) ? red[lane] : 0.0f;
#pragma unroll
        for (int o = 8; o > 0; o >>= 1) x += __shfl_xor_sync(0xFFFFFFFFu, x, o);
        if (lane == 0) *bc = x;
    }
    __syncthreads();
    return *bc;
}

// ---------------------------------------------------------------------------
// Grid barrier: sense-reversing, self-resetting counter + monotonic gen flag.
// ---------------------------------------------------------------------------
__device__ __forceinline__ void gridSync(unsigned& gen) {
    __syncthreads();
    if (threadIdx.x == 0) {
        __threadfence();
        unsigned target = gen + 1;
        unsigned old = atomicAdd(&g_cnt, 1);
        if (old == NCTA - 1) {
            g_cnt = 0;
            __threadfence();
            g_gen = target;
        } else {
            while (g_gen != target) { __nanosleep(32); }
        }
        __threadfence();
        gen = target;
    }
    __syncthreads();
}

// ---------------------------------------------------------------------------
// Round K to fp16 (once per launch)
// ---------------------------------------------------------------------------
__global__ void k_split(const float* __restrict__ K) {
    size_t i0 = (size_t)blockIdx.x * blockDim.x + threadIdx.x;
    size_t stride = (size_t)gridDim.x * blockDim.x;
    size_t n8 = (size_t)NN * NN / 8;
    for (size_t i = i0; i < n8; i += stride) {
        float4 a = ((const float4*)K)[2 * i];
        float4 b = ((const float4*)K)[2 * i + 1];
        union { __half h[8]; uint4 u; } H;
        H.h[0] = __float2half_rn(a.x); H.h[1] = __float2half_rn(a.y);
        H.h[2] = __float2half_rn(a.z); H.h[3] = __float2half_rn(a.w);
        H.h[4] = __float2half_rn(b.x); H.h[5] = __float2half_rn(b.y);
        H.h[6] = __float2half_rn(b.z); H.h[7] = __float2half_rn(b.w);
        ((uint4*)g_Khi16)[i] = H.u;
    }
}

// ---------------------------------------------------------------------------
// Init: B = [y | Z | 0-pad]; Ph/Pl = fp16 split of B (scale 1), R = B, X = 0
// ---------------------------------------------------------------------------
__global__ void k_init(const float* __restrict__ y, const float* __restrict__ Z) {
    int stride = gridDim.x * blockDim.x;
    for (int idx = blockIdx.x * blockDim.x + threadIdx.x; idx < MP * NN; idx += stride) {
        int col = idx >> 13;
        int row = idx & (NN - 1);
        float v = 0.0f;
        if (col == 0)        v = y[row];
        else if (col <= 100) v = Z[row * 100 + (col - 1)];
        __half h = __float2half_rn(v);
        g_Ph16[idx] = h;
        g_Pl16[idx] = __float2half_rn(v - __half2float(h));
        g_R[idx] = v;
        if (col == 0) g_X[row] = 0.0f;
    }
}

// ---------------------------------------------------------------------------
// TMA producer: fill stage (F % NSTG) with A tile + both B tiles.
// Single thread. F = global monotonic fill index; t_in_it = F - it*KITERS.
// ---------------------------------------------------------------------------
__device__ __forceinline__ void produce(uint32_t sb, int F, int t_in_it,
                                        int kbase, int rb,
                                        const CUtensorMap* mK,
                                        const CUtensorMap* mBh,
                                        const CUtensorMap* mBl) {
    uint32_t s = (uint32_t)(F % NSTG);
    uint32_t full = sb + s * 8;
    uint32_t empty = sb + 32 + s * 8;
    if (F >= NSTG) mbar_wait(empty, (uint32_t)((F / NSTG - 1) & 1));
    FENCE_ASYNC();
    MBAR_EXPECT_TX(full, (uint32_t)STAGE_B);
    uint32_t st = sb + 1024 + s * STAGE_B;
    int k0 = kbase + t_in_it * KT;
    TMA2D(st, mK, k0, rb, full);
    TMA2D(st + A_B, mBh, k0, 0, full);
    TMA2D(st + A_B + B_B, mBl, k0, 0, full);
}

// ---------------------------------------------------------------------------
// Persistent kernel: 30 x (GEMM phase -> gridSync -> update phase -> gridSync)
// 128 CTAs x 512 threads (1/SM). GEMM tiles loaded by TMA (no LSU wall).
// ---------------------------------------------------------------------------
__global__ void __launch_bounds__(512) k_persist(
        const __grid_constant__ CUtensorMap tmK,
        const __grid_constant__ CUtensorMap tmBh,
        const __grid_constant__ CUtensorMap tmBl) {
    extern __shared__ __align__(1024) char smem[];
    uint32_t sb = smem_u32(smem);
    volatile float* red = (volatile float*)(smem + 128);   // 16 floats
    volatile float* bcp = (volatile float*)(smem + 256);

    int tid = threadIdx.x, lane = tid & 31, w = tid >> 5;
    int wm = w & 3, wn = w >> 2;
    int bid = blockIdx.x;
    int rb = (bid & 31) * ROWB;
    int ksp = bid >> 5;
    int kbase = ksp * KCHUNK;

    // init mbarriers: full[s] count 1 (expect_tx), empty[s] count 512
    if (tid == 0) {
#pragma unroll
        for (int s = 0; s < NSTG; s++) {
            MBAR_INIT(sb + s * 8, 1u);
            MBAR_INIT(sb + 32 + s * 8, 512u);
        }
    }
    __syncthreads();

    unsigned gen = g_gen;   // safe: read before any barrier can complete

    int rA = wm * 64 + (lane & 15);
    int rB = wn * 32 + (lane & 15);
    int chHalf = lane >> 4;

    // per-column CG state in registers (uniform across the CTA)
    float rs = 0.0f, csc = 1.0f;
    if (bid < MREAL) {
        const float4* R4 = (const float4*)(g_R + (size_t)bid * NN);
        float s = 0.0f;
#pragma unroll
        for (int t = 0; t < 4; t++) {
            float4 rv = R4[t * 512 + tid];
            s += rv.x * rv.x + rv.y * rv.y + rv.z * rv.z + rv.w * rv.w;
        }
        rs = fastReduce512(s, red, bcp);
    }
    __syncthreads();

    for (int it = 0; it < PITER; it++) {
        // ------------------------------ GEMM phase ------------------------
        float acc[4][4][4];
#pragma unroll
        for (int mi = 0; mi < 4; mi++)
#pragma unroll
            for (int nj = 0; nj < 4; nj++)
#pragma unroll
                for (int q = 0; q < 4; q++) acc[mi][nj][q] = 0.0f;

        int Fbase = it * KITERS;
        if (tid == 0) {
            produce(sb, Fbase, 0, kbase, rb, &tmK, &tmBh, &tmBl);
            produce(sb, Fbase + 1, 1, kbase, rb, &tmK, &tmBh, &tmBl);
        }

        for (int t = 0; t < KITERS; t++) {
            int F = Fbase + t;
            if (tid == 0 && t + 2 < KITERS)
                produce(sb, F + 2, t + 2, kbase, rb, &tmK, &tmBh, &tmBl);

            uint32_t s = (uint32_t)(F % NSTG);
            mbar_wait(sb + s * 8, (uint32_t)((F / NSTG) & 1));
            uint32_t st = sb + 1024 + s * STAGE_B;

#pragma unroll
            for (int kk = 0; kk < 4; kk++) {
                int ch = kk * 2 + chHalf;
                uint32_t ah[4][4], bh[2][4], bl[2][4];
#pragma unroll
                for (int i = 0; i < 4; i++)
                    ldsm_x4(ah[i], st + SWZ(rA + i * 16, ch));
                ldsm_x4(bh[0], st + A_B + SWZ(rB, ch));
                ldsm_x4(bh[1], st + A_B + SWZ(rB + 16, ch));
                ldsm_x4(bl[0], st + A_B + B_B + SWZ(rB, ch));
                ldsm_x4(bl[1], st + A_B + B_B + SWZ(rB + 16, ch));
#pragma unroll
                for (int mi = 0; mi < 4; mi++)
#pragma unroll
                    for (int nj = 0; nj < 4; nj++) {
                        int g = nj >> 1, sel = nj & 1;
                        mma16816(acc[mi][nj], ah[mi], bh[g][sel], bh[g][sel + 2]);
                        mma16816(acc[mi][nj], ah[mi], bl[g][sel], bl[g][sel + 2]);
                    }
            }
            MBAR_ARRIVE(sb + 32 + s * 8);
        }

        {   // epilogue: scatter accumulators to Vpart (col-major [col][row])
            float* vp = g_Vpart + (size_t)ksp * MP * NN;
            int row0 = rb + wm * 64 + (lane >> 2);
            int col0 = wn * 32 + (lane & 3) * 2;
#pragma unroll
            for (int mi = 0; mi < 4; mi++)
#pragma unroll
                for (int nj = 0; nj < 4; nj++) {
                    int r_ = row0 + mi * 16;
                    int c_ = col0 + nj * 8;
                    vp[(size_t)c_ * NN + r_]           = acc[mi][nj][0];
                    vp[(size_t)(c_ + 1) * NN + r_]     = acc[mi][nj][1];
                    vp[(size_t)c_ * NN + r_ + 8]       = acc[mi][nj][2];
                    vp[(size_t)(c_ + 1) * NN + r_ + 8] = acc[mi][nj][3];
                }
        }

        gridSync(gen);   // Vpart complete before update reads it

        // ------------------------------ update phase ----------------------
        if (bid < MREAL) {
            int j = bid;
            const float4* V0 = (const float4*)g_Vpart + (size_t)j * NN / 4;
            const size_t PL = (size_t)MP * NN / 4;
            const float4* R4 = (const float4*)(g_R + (size_t)j * NN);
            const uint2* Ph2 = (const uint2*)(g_Ph16 + (size_t)j * NN);
            const uint2* Pl2 = (const uint2*)(g_Pl16 + (size_t)j * NN);

            float4 p[4], v[4], r[4];
            float pv = 0.0f;
#pragma unroll
            for (int t = 0; t < 4; t++) {
                int i4 = t * 512 + tid;
                float4 a = __ldcg(V0 + i4);
                float4 b = __ldcg(V0 + PL + i4);
                float4 d2 = __ldcg(V0 + 2 * PL + i4);
                float4 e2 = __ldcg(V0 + 3 * PL + i4);
                float4 s = make_float4(a.x + b.x + d2.x + e2.x,
                                       a.y + b.y + d2.y + e2.y,
                                       a.z + b.z + d2.z + e2.z,
                                       a.w + b.w + d2.w + e2.w);
                v[t] = s;
                uint2 hu = Ph2[i4], lu = Pl2[i4];
                __half2 h0 = *(__half2*)&hu.x, h1 = *(__half2*)&hu.y;
                __half2 l0 = *(__half2*)&lu.x, l1 = *(__half2*)&lu.y;
                float2 f0 = __half22float2(h0), f1 = __half22float2(h1);
                float2 g0 = __half22float2(l0), g1 = __half22float2(l1);
                float4 pp = make_float4(f0.x + g0.x, f0.y + g0.y,
                                        f1.x + g1.x, f1.y + g1.y);
                p[t] = pp;
                pv += pp.x * s.x + pp.y * s.y + pp.z * s.z + pp.w * s.w;
            }
            pv = fastReduce512(pv, red, bcp);      // = c^2 * (P.V)
            float alpha = rs * csc * csc / pv;
            float aoc = alpha / csc;

            float rr = 0.0f;
#pragma unroll
            for (int t = 0; t < 4; t++) {
                int i4 = t * 512 + tid;
                float4 rv = R4[i4];
                rv.x -= aoc * v[t].x; rv.y -= aoc * v[t].y;
                rv.z -= aoc * v[t].z; rv.w -= aoc * v[t].w;
                r[t] = rv;
                rr += rv.x * rv.x + rv.y * rv.y + rv.z * rv.z + rv.w * rv.w;
            }
            if (j == 0) {
                float4* X4 = (float4*)g_X;
#pragma unroll
                for (int t = 0; t < 4; t++) {
                    int i4 = t * 512 + tid;
                    float4 x = X4[i4];
                    x.x += aoc * p[t].x; x.y += aoc * p[t].y;
                    x.z += aoc * p[t].z; x.w += aoc * p[t].w;
                    X4[i4] = x;
                }
            }
            rr = fastReduce512(rr, red, bcp);
            float beta = rr / rs;
            float c2 = exp2f(-rintf(0.5f * log2f(rr * (1.0f / (float)NN))));
            if (tid == 0) {
                g_alpha[it * MP + j] = alpha;
                g_beta[it * MP + j]  = beta;
            }
            float boc = beta / csc;

            uint2* Phw = (uint2*)(g_Ph16 + (size_t)j * NN);
            uint2* Plw = (uint2*)(g_Pl16 + (size_t)j * NN);
            float4* Rw = (float4*)(g_R + (size_t)j * NN);
#pragma unroll
            for (int t = 0; t < 4; t++) {
                int i4 = t * 512 + tid;
                float pn[4] = {
                    r[t].x + boc * p[t].x, r[t].y + boc * p[t].y,
                    r[t].z + boc * p[t].z, r[t].w + boc * p[t].w };
                __half hh[4]; float ll[4];
#pragma unroll
                for (int q = 0; q < 4; q++) {
                    float ps = c2 * pn[q];
                    hh[q] = __float2half_rn(ps);
                    ll[q] = ps - __half2float(hh[q]);
                }
                uint2 hu, lu;
                __half2 t0 = __halves2half2(hh[0], hh[1]);
                __half2 t1 = __halves2half2(hh[2], hh[3]);
                hu.x = *(uint32_t*)&t0; hu.y = *(uint32_t*)&t1;
                __half2 u0 = __floats2half2_rn(ll[0], ll[1]);
                __half2 u1 = __floats2half2_rn(ll[2], ll[3]);
                lu.x = *(uint32_t*)&u0; lu.y = *(uint32_t*)&u1;
                Phw[i4] = hu;
                Plw[i4] = lu;
                Rw[i4] = r[t];
            }
            rs = rr;
            csc = c2;
        }

        gridSync(gen);   // P complete before next GEMM reads it / Vpart reuse
    }
}

// ---------------------------------------------------------------------------
// SLQ logdet (TQLI on 30x30 tridiagonal, first-row eigenvector weights)
// ---------------------------------------------------------------------------
__device__ void tqli30(double* d, double* e, double* z) {
    const int n = PITER;
    for (int l = 0; l < n; l++) {
        int iter = 0;
        int m;
        do {
            for (m = l; m < n - 1; m++) {
                double dd = fabs(d[m]) + fabs(d[m + 1]);
                if (fabs(e[m]) <= 2.3e-16 * dd) break;
            }
            if (m != l) {
                if (iter++ == 64) break;
                double g = (d[l + 1] - d[l]) / (2.0 * e[l]);
                double rr = sqrt(g * g + 1.0);
                double sg = (g >= 0.0) ? rr : -rr;
                g = d[m] - d[l] + e[l] / (g + sg);
                double s = 1.0, cc = 1.0, p = 0.0;
                bool under = false;
                for (int i = m - 1; i >= l; i--) {
                    double f = s * e[i];
                    double b = cc * e[i];
                    double rq = sqrt(f * f + g * g);
                    e[i + 1] = rq;
                    if (rq == 0.0) {
                        d[i + 1] -= p;
                        e[m] = 0.0;
                        under = true;
                        break;
                    }
                    s = f / rq; cc = g / rq;
                    g = d[i + 1] - p;
                    rq = (d[i] - g) * s + 2.0 * cc * b;
                    p = s * rq;
                    d[i + 1] = g + p;
                    g = cc * rq - b;
                    double zi = z[i], zi1 = z[i + 1];
                    z[i + 1] = s * zi + cc * zi1;
                    z[i]     = cc * zi - s * zi1;
                }
                if (under) continue;
                d[l] -= p;
                e[l] = g;
                e[m] = 0.0;
            }
        } while (m != l);
    }
}

__global__ void k_logdet() {
    __shared__ double qsum[128];
    int tid = threadIdx.x;
    double quad = 0.0;
    if (tid < 100) {
        int j = tid + 1;
        double d[PITER], e[PITER], z[PITER];
        double pa = 1.0, pb = 0.0;
        for (int k = 0; k < PITER; k++) {
            double a = (double)g_alpha[k * MP + j];
            double b = (double)g_beta[k * MP + j];
            d[k] = 1.0 / a + ((k > 0) ? pb / pa : 0.0);
            e[k] = (k < PITER - 1) ? sqrt(b) / a : 0.0;
            z[k] = (k == 0) ? 1.0 : 0.0;
            pa = a; pb = b;
        }
        tqli30(d, e, z);
        for (int k = 0; k < PITER; k++) {
            double lam = d[k] < 1e-12 ? 1e-12 : d[k];
            quad += z[k] * z[k] * log(lam);
        }
    }
    qsum[tid] = quad;
    __syncthreads();
    if (tid == 0) {
        double s = 0.0;
        for (int i = 0; i < 100; i++) s += qsum[i];
        g_logdet = (float)((double)NN * s / 100.0);
    }
}

__global__ void k_final(const float* __restrict__ y, float* __restrict__ out) {
    __shared__ float red[256];
    float s = 0.0f;
    for (int i = threadIdx.x; i < NN; i += 256) s += y[i] * g_X[i];
    s = blockReduce<256>(s, red);
    if (threadIdx.x == 0) {
        const double LOG2PI = 1.8378770664093454836;
        double r = -0.5 * (double)s - 0.5 * (double)g_logdet - 0.5 * (double)NN * LOG2PI;
        out[0] = (float)r;
    }
}

// ---------------------------------------------------------------------------
// Launch: build TensorMaps via driver entry point (cudart-only), then chain.
// ---------------------------------------------------------------------------
typedef CUresult (*PFN_encodeTiled)(
    CUtensorMap*, CUtensorMapDataType, cuuint32_t, void*,
    const cuuint64_t*, const cuuint64_t*, const cuuint32_t*, const cuuint32_t*,
    CUtensorMapInterleave, CUtensorMapSwizzle, CUtensorMapL2promotion,
    CUtensorMapFloatOOBfill);

extern "C" void kernel_launch(void* const* d_in, const int* in_sizes, int n_in,
                              void* d_out, int out_size) {
    const float* K = (const float*)d_in[0];
    const float* y = (const float*)d_in[1];
    const float* Z = (const float*)d_in[2];
    float* out = (float*)d_out;

    // resolve cuTensorMapEncodeTiled through cudart (no -lcuda needed)
    void* fn = nullptr;
    cudaDriverEntryPointQueryResult qres;
    cudaGetDriverEntryPointByVersion("cuTensorMapEncodeTiled", &fn, 12000,
                                     cudaEnableDefault, &qres);
    PFN_encodeTiled enc = (PFN_encodeTiled)fn;

    void *pK = nullptr, *pPh = nullptr, *pPl = nullptr;
    cudaGetSymbolAddress(&pK, g_Khi16);
    cudaGetSymbolAddress(&pPh, g_Ph16);
    cudaGetSymbolAddress(&pPl, g_Pl16);

    CUtensorMap tmK, tmBh, tmBl;
    {
        cuuint64_t dims[2] = {NN, NN};
        cuuint64_t strides[1] = {NN * 2};
        cuuint32_t box[2] = {64, 256};
        cuuint32_t es[2] = {1, 1};
        enc(&tmK, CU_TENSOR_MAP_DATA_TYPE_FLOAT16, 2, pK, dims, strides, box, es,
            CU_TENSOR_MAP_INTERLEAVE_NONE, CU_TENSOR_MAP_SWIZZLE_128B,
            CU_TENSOR_MAP_L2_PROMOTION_L2_128B, CU_TENSOR_MAP_FLOAT_OOB_FILL_NONE);
    }
    {
        cuuint64_t dims[2] = {NN, MP};
        cuuint64_t strides[1] = {NN * 2};
        cuuint32_t box[2] = {64, 128};
        cuuint32_t es[2] = {1, 1};
        enc(&tmBh, CU_TENSOR_MAP_DATA_TYPE_FLOAT16, 2, pPh, dims, strides, box, es,
            CU_TENSOR_MAP_INTERLEAVE_NONE, CU_TENSOR_MAP_SWIZZLE_128B,
            CU_TENSOR_MAP_L2_PROMOTION_L2_128B, CU_TENSOR_MAP_FLOAT_OOB_FILL_NONE);
        enc(&tmBl, CU_TENSOR_MAP_DATA_TYPE_FLOAT16, 2, pPl, dims, strides, box, es,
            CU_TENSOR_MAP_INTERLEAVE_NONE, CU_TENSOR_MAP_SWIZZLE_128B,
            CU_TENSOR_MAP_L2_PROMOTION_L2_128B, CU_TENSOR_MAP_FLOAT_OOB_FILL_NONE);
    }

    cudaFuncSetAttribute(k_persist, cudaFuncAttributeMaxDynamicSharedMemorySize,
                         SMEM_DYN);

    k_split<<<4096, 256>>>(K);
    k_init<<<512, 256>>>(y, Z);
    k_persist<<<NCTA, 512, SMEM_DYN>>>(tmK, tmBh, tmBl);
    k_logdet<<<1, 128>>>();
    k_final<<<1, 256>>>(y, out);
}

// round 9
// speedup vs baseline: 1.9804x; 1.3219x over previous
#include <cuda.h>
#include <cuda_runtime.h>
#include <cuda_fp16.h>
#include <math.h>
#include <stdint.h>

// ---------------------------------------------------------------------------
// Problem constants
// ---------------------------------------------------------------------------
#define NN      8192
#define MREAL   101
#define MP      128
#define PITER   30
#define KSPLIT  4
#define KCHUNK  (NN / KSPLIT)        // 2048
#define KT      64                   // k per pipeline stage
#define KITERS  (KCHUNK / KT)        // 32
#define NSTG    4
#define ROWB    256
#define NCTA    128                  // 32 rowblocks x KSPLIT, 1 CTA/SM
#define A_B     (ROWB * KT * 2)      // 32768 B: A tile (256 rows x 64 k fp16)
#define B_B     (128 * KT * 2)       // 16384 B: B tile (128 cols x 64 k)
#define STAGE_B (A_B + B_B)          // 49152 B
#define SMEM_DYN (1024 + NSTG * STAGE_B)   // 197632 B

// ---------------------------------------------------------------------------
// Scratch (static device globals; no allocation allowed)
// ---------------------------------------------------------------------------
__device__ __half g_Khi16[(size_t)NN * NN];     // 128 MB: fp16-rounded K
__device__ __half g_Ph16[(size_t)MP * NN];      // scaled fp16 P, col-major
__device__ float  g_R[(size_t)MP * NN];
__device__ float  g_X[NN];
__device__ float  g_Vpart[(size_t)KSPLIT * MP * NN];  // 16 MB
__device__ float  g_alpha[PITER * MP];
__device__ float  g_beta[PITER * MP];
__device__ float  g_logdet;

// grid barrier state (self-resetting; g_gen monotonic across graph replays)
__device__ unsigned g_cnt = 0;
__device__ volatile unsigned g_gen = 0;

// ---------------------------------------------------------------------------
// PTX helpers (family-portable: ldmatrix / mma.sync / TMA / mbarrier)
// ---------------------------------------------------------------------------
__device__ __forceinline__ uint32_t smem_u32(const void* p) {
    uint32_t a;
    asm("{ .reg .u64 t; cvta.to.shared.u64 t, %1; cvt.u32.u64 %0, t; }"
        : "=r"(a) : "l"(p));
    return a;
}

__device__ __forceinline__ void ldsm_x4(uint32_t (&r)[4], uint32_t addr) {
    asm volatile("ldmatrix.sync.aligned.m8n8.x4.shared.b16 {%0,%1,%2,%3}, [%4];"
        : "=r"(r[0]), "=r"(r[1]), "=r"(r[2]), "=r"(r[3]) : "r"(addr));
}

__device__ __forceinline__ void mma16816(float (&d)[4], const uint32_t (&a)[4],
                                         uint32_t b0, uint32_t b1) {
    asm volatile("mma.sync.aligned.m16n8k16.row.col.f32.f16.f16.f32 "
        "{%0,%1,%2,%3}, {%4,%5,%6,%7}, {%8,%9}, {%0,%1,%2,%3};"
        : "+f"(d[0]), "+f"(d[1]), "+f"(d[2]), "+f"(d[3])
        : "r"(a[0]), "r"(a[1]), "r"(a[2]), "r"(a[3]), "r"(b0), "r"(b1));
}

#define MBAR_INIT(addr, cnt) \
    asm volatile("mbarrier.init.shared.b64 [%0], %1;" :: "r"(addr), "r"(cnt) : "memory")
#define MBAR_ARRIVE(addr) \
    asm volatile("mbarrier.arrive.shared.b64 _, [%0];" :: "r"(addr) : "memory")
#define MBAR_EXPECT_TX(addr, bytes) \
    asm volatile("mbarrier.arrive.expect_tx.shared.b64 _, [%0], %1;" \
                 :: "r"(addr), "r"(bytes) : "memory")

__device__ __forceinline__ void mbar_wait(uint32_t addr, uint32_t parity) {
    asm volatile(
        "{\n\t.reg .pred p;\n\t"
        "WAIT_%=:\n\t"
        "mbarrier.try_wait.parity.shared.b64 p, [%0], %1;\n\t"
        "@!p bra WAIT_%=;\n\t}"
        :: "r"(addr), "r"(parity) : "memory");
}

#define TMA2D(smem, map, x, y, mbar) \
    asm volatile("cp.async.bulk.tensor.2d.shared::cta.global.tile.mbarrier::complete_tx::bytes " \
                 "[%0], [%1, {%2, %3}], [%4];" \
                 :: "r"(smem), "l"(map), "r"(x), "r"(y), "r"(mbar) : "memory")

#define FENCE_ASYNC() asm volatile("fence.proxy.async.shared::cta;" ::: "memory")

// Swizzle matching CU_TENSOR_MAP_SWIZZLE_128B with 128B rows
// (r = row, ch = 16B chunk 0..7): byte_off ^ ((byte_off>>3)&0x70)
#define SWZ(r, ch) (((r) << 7) + ((((ch) ^ ((r) & 7))) << 4))

// ---------------------------------------------------------------------------
// Reductions
// ---------------------------------------------------------------------------
template <int BS>
__device__ __forceinline__ float blockReduce(float v, float* red) {
    int tid = threadIdx.x;
    red[tid] = v;
    __syncthreads();
#pragma unroll
    for (int s = BS / 2; s > 0; s >>= 1) {
        if (tid < s) red[tid] += red[tid + s];
        __syncthreads();
    }
    float out = red[0];
    __syncthreads();
    return out;
}

__device__ __forceinline__ float fastReduce512(float v, volatile float* red,
                                               volatile float* bc) {
    int lane = threadIdx.x & 31, wid = threadIdx.x >> 5;
#pragma unroll
    for (int o = 16; o > 0; o >>= 1) v += __shfl_xor_sync(0xFFFFFFFFu, v, o);
    if (lane == 0) red[wid] = v;
    __syncthreads();
    if (wid == 0) {
        float x = (lane < 16) ? red[lane] : 0.0f;
#pragma unroll
        for (int o = 8; o > 0; o >>= 1) x += __shfl_xor_sync(0xFFFFFFFFu, x, o);
        if (lane == 0) *bc = x;
    }
    __syncthreads();
    return *bc;
}

// ---------------------------------------------------------------------------
// Grid barrier: sense-reversing, self-resetting counter + monotonic gen flag.
// ---------------------------------------------------------------------------
__device__ __forceinline__ void gridSync(unsigned& gen) {
    __syncthreads();
    if (threadIdx.x == 0) {
        __threadfence();
        unsigned target = gen + 1;
        unsigned old = atomicAdd(&g_cnt, 1);
        if (old == NCTA - 1) {
            g_cnt = 0;
            __threadfence();
            g_gen = target;
        } else {
            while (g_gen != target) { __nanosleep(32); }
        }
        __threadfence();
        gen = target;
    }
    __syncthreads();
}

// ---------------------------------------------------------------------------
// Round K to fp16 (once per launch)
// ---------------------------------------------------------------------------
__global__ void k_split(const float* __restrict__ K) {
    size_t i0 = (size_t)blockIdx.x * blockDim.x + threadIdx.x;
    size_t stride = (size_t)gridDim.x * blockDim.x;
    size_t n8 = (size_t)NN * NN / 8;
    for (size_t i = i0; i < n8; i += stride) {
        float4 a = ((const float4*)K)[2 * i];
        float4 b = ((const float4*)K)[2 * i + 1];
        union { __half h[8]; uint4 u; } H;
        H.h[0] = __float2half_rn(a.x); H.h[1] = __float2half_rn(a.y);
        H.h[2] = __float2half_rn(a.z); H.h[3] = __float2half_rn(a.w);
        H.h[4] = __float2half_rn(b.x); H.h[5] = __float2half_rn(b.y);
        H.h[6] = __float2half_rn(b.z); H.h[7] = __float2half_rn(b.w);
        ((uint4*)g_Khi16)[i] = H.u;
    }
}

// ---------------------------------------------------------------------------
// Init: B = [y | Z | 0-pad]; P = fp16(B) (scale 1), R = B, X = 0
// ---------------------------------------------------------------------------
__global__ void k_init(const float* __restrict__ y, const float* __restrict__ Z) {
    int stride = gridDim.x * blockDim.x;
    for (int idx = blockIdx.x * blockDim.x + threadIdx.x; idx < MP * NN; idx += stride) {
        int col = idx >> 13;
        int row = idx & (NN - 1);
        float v = 0.0f;
        if (col == 0)        v = y[row];
        else if (col <= 100) v = Z[row * 100 + (col - 1)];
        g_Ph16[idx] = __float2half_rn(v);
        g_R[idx] = v;
        if (col == 0) g_X[row] = 0.0f;
    }
}

// ---------------------------------------------------------------------------
// TMA producer: fill stage (F % NSTG) with A tile + B tile. Single thread.
// ---------------------------------------------------------------------------
__device__ __forceinline__ void produce(uint32_t sb, int F, int t_in_it,
                                        int kbase, int rb,
                                        const CUtensorMap* mK,
                                        const CUtensorMap* mB) {
    uint32_t s = (uint32_t)(F % NSTG);
    uint32_t full = sb + s * 8;
    uint32_t empty = sb + 64 + s * 8;
    if (F >= NSTG) mbar_wait(empty, (uint32_t)((F / NSTG - 1) & 1));
    FENCE_ASYNC();
    MBAR_EXPECT_TX(full, (uint32_t)STAGE_B);
    uint32_t st = sb + 1024 + s * STAGE_B;
    int k0 = kbase + t_in_it * KT;
    TMA2D(st, mK, k0, rb, full);
    TMA2D(st + A_B, mB, k0, 0, full);
}

// ---------------------------------------------------------------------------
// Persistent kernel: 30 x (GEMM phase -> gridSync -> update phase -> gridSync)
// 128 CTAs x 512 threads (1/SM). Single-product GEMM: V = fp16(K) @ fp16(P).
// ---------------------------------------------------------------------------
__global__ void __launch_bounds__(512) k_persist(
        const __grid_constant__ CUtensorMap tmK,
        const __grid_constant__ CUtensorMap tmB) {
    extern __shared__ __align__(1024) char smem[];
    uint32_t sb = smem_u32(smem);
    volatile float* red = (volatile float*)(smem + 128);   // 16 floats
    volatile float* bcp = (volatile float*)(smem + 256);

    int tid = threadIdx.x, lane = tid & 31, w = tid >> 5;
    int wm = w & 3, wn = w >> 2;
    int bid = blockIdx.x;
    int rb = (bid & 31) * ROWB;
    int ksp = bid >> 5;
    int kbase = ksp * KCHUNK;

    // init mbarriers: full[s] count 1 (expect_tx), empty[s] count 512
    if (tid == 0) {
#pragma unroll
        for (int s = 0; s < NSTG; s++) {
            MBAR_INIT(sb + s * 8, 1u);
            MBAR_INIT(sb + 64 + s * 8, 512u);
        }
    }
    __syncthreads();

    unsigned gen = g_gen;   // safe: read before any barrier can complete

    int rA = wm * 64 + (lane & 15);
    int rB = wn * 32 + (lane & 15);
    int chHalf = lane >> 4;

    // per-column CG state in registers (uniform across the CTA)
    float rs = 0.0f, csc = 1.0f;
    if (bid < MREAL) {
        const float4* R4 = (const float4*)(g_R + (size_t)bid * NN);
        float s = 0.0f;
#pragma unroll
        for (int t = 0; t < 4; t++) {
            float4 rv = R4[t * 512 + tid];
            s += rv.x * rv.x + rv.y * rv.y + rv.z * rv.z + rv.w * rv.w;
        }
        rs = fastReduce512(s, red, bcp);
    }
    __syncthreads();

    for (int it = 0; it < PITER; it++) {
        // ------------------------------ GEMM phase ------------------------
        float acc[4][4][4];
#pragma unroll
        for (int mi = 0; mi < 4; mi++)
#pragma unroll
            for (int nj = 0; nj < 4; nj++)
#pragma unroll
                for (int q = 0; q < 4; q++) acc[mi][nj][q] = 0.0f;

        int Fbase = it * KITERS;
        if (tid == 0) {
            produce(sb, Fbase, 0, kbase, rb, &tmK, &tmB);
            produce(sb, Fbase + 1, 1, kbase, rb, &tmK, &tmB);
            produce(sb, Fbase + 2, 2, kbase, rb, &tmK, &tmB);
        }

        for (int t = 0; t < KITERS; t++) {
            int F = Fbase + t;
            if (tid == 0 && t + 3 < KITERS)
                produce(sb, F + 3, t + 3, kbase, rb, &tmK, &tmB);

            uint32_t s = (uint32_t)(F % NSTG);
            mbar_wait(sb + s * 8, (uint32_t)((F / NSTG) & 1));
            uint32_t st = sb + 1024 + s * STAGE_B;

#pragma unroll
            for (int kk = 0; kk < 4; kk++) {
                int ch = kk * 2 + chHalf;
                uint32_t ah[4][4], bh[2][4];
#pragma unroll
                for (int i = 0; i < 4; i++)
                    ldsm_x4(ah[i], st + SWZ(rA + i * 16, ch));
                ldsm_x4(bh[0], st + A_B + SWZ(rB, ch));
                ldsm_x4(bh[1], st + A_B + SWZ(rB + 16, ch));
#pragma unroll
                for (int mi = 0; mi < 4; mi++)
#pragma unroll
                    for (int nj = 0; nj < 4; nj++) {
                        int g = nj >> 1, sel = nj & 1;
                        mma16816(acc[mi][nj], ah[mi], bh[g][sel], bh[g][sel + 2]);
                    }
            }
            MBAR_ARRIVE(sb + 64 + s * 8);
        }

        {   // epilogue: scatter accumulators to Vpart (col-major [col][row])
            float* vp = g_Vpart + (size_t)ksp * MP * NN;
            int row0 = rb + wm * 64 + (lane >> 2);
            int col0 = wn * 32 + (lane & 3) * 2;
#pragma unroll
            for (int mi = 0; mi < 4; mi++)
#pragma unroll
                for (int nj = 0; nj < 4; nj++) {
                    int r_ = row0 + mi * 16;
                    int c_ = col0 + nj * 8;
                    vp[(size_t)c_ * NN + r_]           = acc[mi][nj][0];
                    vp[(size_t)(c_ + 1) * NN + r_]     = acc[mi][nj][1];
                    vp[(size_t)c_ * NN + r_ + 8]       = acc[mi][nj][2];
                    vp[(size_t)(c_ + 1) * NN + r_ + 8] = acc[mi][nj][3];
                }
        }

        gridSync(gen);   // Vpart complete before update reads it

        // ------------------------------ update phase ----------------------
        if (bid < MREAL) {
            int j = bid;
            const float4* V0 = (const float4*)g_Vpart + (size_t)j * NN / 4;
            const size_t PL = (size_t)MP * NN / 4;
            const float4* R4 = (const float4*)(g_R + (size_t)j * NN);
            const uint2* Ph2 = (const uint2*)(g_Ph16 + (size_t)j * NN);

            float4 p[4], v[4], r[4];
            float pv = 0.0f;
#pragma unroll
            for (int t = 0; t < 4; t++) {
                int i4 = t * 512 + tid;
                float4 a = __ldcg(V0 + i4);
                float4 b = __ldcg(V0 + PL + i4);
                float4 d2 = __ldcg(V0 + 2 * PL + i4);
                float4 e2 = __ldcg(V0 + 3 * PL + i4);
                float4 s = make_float4(a.x + b.x + d2.x + e2.x,
                                       a.y + b.y + d2.y + e2.y,
                                       a.z + b.z + d2.z + e2.z,
                                       a.w + b.w + d2.w + e2.w);
                v[t] = s;
                uint2 hu = Ph2[i4];
                __half2 h0 = *(__half2*)&hu.x, h1 = *(__half2*)&hu.y;
                float2 f0 = __half22float2(h0), f1 = __half22float2(h1);
                float4 pp = make_float4(f0.x, f0.y, f1.x, f1.y);
                p[t] = pp;
                pv += pp.x * s.x + pp.y * s.y + pp.z * s.z + pp.w * s.w;
            }
            pv = fastReduce512(pv, red, bcp);      // = c^2 * (P.V)
            float alpha = rs * csc * csc / pv;
            float aoc = alpha / csc;

            float rr = 0.0f;
#pragma unroll
            for (int t = 0; t < 4; t++) {
                int i4 = t * 512 + tid;
                float4 rv = R4[i4];
                rv.x -= aoc * v[t].x; rv.y -= aoc * v[t].y;
                rv.z -= aoc * v[t].z; rv.w -= aoc * v[t].w;
                r[t] = rv;
                rr += rv.x * rv.x + rv.y * rv.y + rv.z * rv.z + rv.w * rv.w;
            }
            if (j == 0) {
                float4* X4 = (float4*)g_X;
#pragma unroll
                for (int t = 0; t < 4; t++) {
                    int i4 = t * 512 + tid;
                    float4 x = X4[i4];
                    x.x += aoc * p[t].x; x.y += aoc * p[t].y;
                    x.z += aoc * p[t].z; x.w += aoc * p[t].w;
                    X4[i4] = x;
                }
            }
            rr = fastReduce512(rr, red, bcp);
            float beta = rr / rs;
            float c2 = exp2f(-rintf(0.5f * log2f(rr * (1.0f / (float)NN))));
            if (tid == 0) {
                g_alpha[it * MP + j] = alpha;
                g_beta[it * MP + j]  = beta;
            }
            float boc = beta / csc;

            uint2* Phw = (uint2*)(g_Ph16 + (size_t)j * NN);
            float4* Rw = (float4*)(g_R + (size_t)j * NN);
#pragma unroll
            for (int t = 0; t < 4; t++) {
                int i4 = t * 512 + tid;
                float pn[4] = {
                    r[t].x + boc * p[t].x, r[t].y + boc * p[t].y,
                    r[t].z + boc * p[t].z, r[t].w + boc * p[t].w };
                __half2 t0 = __floats2half2_rn(c2 * pn[0], c2 * pn[1]);
                __half2 t1 = __floats2half2_rn(c2 * pn[2], c2 * pn[3]);
                uint2 hu;
                hu.x = *(uint32_t*)&t0; hu.y = *(uint32_t*)&t1;
                Phw[i4] = hu;
                Rw[i4] = r[t];
            }
            rs = rr;
            csc = c2;
        }

        gridSync(gen);   // P complete before next GEMM reads it / Vpart reuse
    }
}

// ---------------------------------------------------------------------------
// SLQ logdet (TQLI on 30x30 tridiagonal, first-row eigenvector weights)
// ---------------------------------------------------------------------------
__device__ void tqli30(double* d, double* e, double* z) {
    const int n = PITER;
    for (int l = 0; l < n; l++) {
        int iter = 0;
        int m;
        do {
            for (m = l; m < n - 1; m++) {
                double dd = fabs(d[m]) + fabs(d[m + 1]);
                if (fabs(e[m]) <= 2.3e-16 * dd) break;
            }
            if (m != l) {
                if (iter++ == 64) break;
                double g = (d[l + 1] - d[l]) / (2.0 * e[l]);
                double rr = sqrt(g * g + 1.0);
                double sg = (g >= 0.0) ? rr : -rr;
                g = d[m] - d[l] + e[l] / (g + sg);
                double s = 1.0, cc = 1.0, p = 0.0;
                bool under = false;
                for (int i = m - 1; i >= l; i--) {
                    double f = s * e[i];
                    double b = cc * e[i];
                    double rq = sqrt(f * f + g * g);
                    e[i + 1] = rq;
                    if (rq == 0.0) {
                        d[i + 1] -= p;
                        e[m] = 0.0;
                        under = true;
                        break;
                    }
                    s = f / rq; cc = g / rq;
                    g = d[i + 1] - p;
                    rq = (d[i] - g) * s + 2.0 * cc * b;
                    p = s * rq;
                    d[i + 1] = g + p;
                    g = cc * rq - b;
                    double zi = z[i], zi1 = z[i + 1];
                    z[i + 1] = s * zi + cc * zi1;
                    z[i]     = cc * zi - s * zi1;
                }
                if (under) continue;
                d[l] -= p;
                e[l] = g;
                e[m] = 0.0;
            }
        } while (m != l);
    }
}

__global__ void k_logdet() {
    __shared__ double qsum[128];
    int tid = threadIdx.x;
    double quad = 0.0;
    if (tid < 100) {
        int j = tid + 1;
        double d[PITER], e[PITER], z[PITER];
        double pa = 1.0, pb = 0.0;
        for (int k = 0; k < PITER; k++) {
            double a = (double)g_alpha[k * MP + j];
            double b = (double)g_beta[k * MP + j];
            d[k] = 1.0 / a + ((k > 0) ? pb / pa : 0.0);
            e[k] = (k < PITER - 1) ? sqrt(b) / a : 0.0;
            z[k] = (k == 0) ? 1.0 : 0.0;
            pa = a; pb = b;
        }
        tqli30(d, e, z);
        for (int k = 0; k < PITER; k++) {
            double lam = d[k] < 1e-12 ? 1e-12 : d[k];
            quad += z[k] * z[k] * log(lam);
        }
    }
    qsum[tid] = quad;
    __syncthreads();
    if (tid == 0) {
        double s = 0.0;
        for (int i = 0; i < 100; i++) s += qsum[i];
        g_logdet = (float)((double)NN * s / 100.0);
    }
}

__global__ void k_final(const float* __restrict__ y, float* __restrict__ out) {
    __shared__ float red[256];
    float s = 0.0f;
    for (int i = threadIdx.x; i < 256 * 32; i += 256) {
        s += y[i] * g_X[i];
    }
    s = blockReduce<256>(s, red);
    if (threadIdx.x == 0) {
        const double LOG2PI = 1.8378770664093454836;
        double r = -0.5 * (double)s - 0.5 * (double)g_logdet - 0.5 * (double)NN * LOG2PI;
        out[0] = (float)r;
    }
}

// ---------------------------------------------------------------------------
// Launch: build TensorMaps via driver entry point (cudart-only), then chain.
// ---------------------------------------------------------------------------
typedef CUresult (*PFN_encodeTiled)(
    CUtensorMap*, CUtensorMapDataType, cuuint32_t, void*,
    const cuuint64_t*, const cuuint64_t*, const cuuint32_t*, const cuuint32_t*,
    CUtensorMapInterleave, CUtensorMapSwizzle, CUtensorMapL2promotion,
    CUtensorMapFloatOOBfill);

extern "C" void kernel_launch(void* const* d_in, const int* in_sizes, int n_in,
                              void* d_out, int out_size) {
    const float* K = (const float*)d_in[0];
    const float* y = (const float*)d_in[1];
    const float* Z = (const float*)d_in[2];
    float* out = (float*)d_out;

    // resolve cuTensorMapEncodeTiled through cudart (no -lcuda needed)
    void* fn = nullptr;
    cudaDriverEntryPointQueryResult qres;
    cudaGetDriverEntryPointByVersion("cuTensorMapEncodeTiled", &fn, 12000,
                                     cudaEnableDefault, &qres);
    PFN_encodeTiled enc = (PFN_encodeTiled)fn;

    void *pK = nullptr, *pPh = nullptr;
    cudaGetSymbolAddress(&pK, g_Khi16);
    cudaGetSymbolAddress(&pPh, g_Ph16);

    CUtensorMap tmK, tmB;
    {
        cuuint64_t dims[2] = {NN, NN};
        cuuint64_t strides[1] = {NN * 2};
        cuuint32_t box[2] = {64, 256};
        cuuint32_t es[2] = {1, 1};
        enc(&tmK, CU_TENSOR_MAP_DATA_TYPE_FLOAT16, 2, pK, dims, strides, box, es,
            CU_TENSOR_MAP_INTERLEAVE_NONE, CU_TENSOR_MAP_SWIZZLE_128B,
            CU_TENSOR_MAP_L2_PROMOTION_L2_128B, CU_TENSOR_MAP_FLOAT_OOB_FILL_NONE);
    }
    {
        cuuint64_t dims[2] = {NN, MP};
        cuuint64_t strides[1] = {NN * 2};
        cuuint32_t box[2] = {64, 128};
        cuuint32_t es[2] = {1, 1};
        enc(&tmB, CU_TENSOR_MAP_DATA_TYPE_FLOAT16, 2, pPh, dims, strides, box, es,
            CU_TENSOR_MAP_INTERLEAVE_NONE, CU_TENSOR_MAP_SWIZZLE_128B,
            CU_TENSOR_MAP_L2_PROMOTION_L2_128B, CU_TENSOR_MAP_FLOAT_OOB_FILL_NONE);
    }

    cudaFuncSetAttribute(k_persist, cudaFuncAttributeMaxDynamicSharedMemorySize,
                         SMEM_DYN);

    k_split<<<4096, 256>>>(K);
    k_init<<<512, 256>>>(y, Z);
    k_persist<<<NCTA, 512, SMEM_DYN>>>(tmK, tmB);
    k_logdet<<<1, 128>>>();
    k_final<<<1, 256>>>(y, out);
}

// round 10
// speedup vs baseline: 1.9993x; 1.0096x over previous
#include <cuda.h>
#include <cuda_runtime.h>
#include <cuda_fp16.h>
#include <math.h>
#include <stdint.h>

// ---------------------------------------------------------------------------
// Problem constants
// ---------------------------------------------------------------------------
#define NN      8192
#define MREAL   101
#define MP      128
#define NCOLS   104                  // computed columns (13 x 8), >= MREAL
#define PITER   30
#define KSPLIT  4
#define KCHUNK  (NN / KSPLIT)        // 2048
#define KT      64                   // k per pipeline stage
#define KITERS  (KCHUNK / KT)        // 32
#define NSTG    4
#define ROWB    256
#define NCTA    128                  // 32 rowblocks x KSPLIT, 1 CTA/SM
#define A_B     (ROWB * KT * 2)      // 32768 B: A tile (256 rows x 64 k fp16)
#define B_TX    (NCOLS * KT * 2)     // 13312 B actually transferred
#define B_SP    (112 * KT * 2)       // 14336 B reserved (ldsm overread pad)
#define STAGE_SP (A_B + B_SP)        // 47104 B layout stride (1024-aligned)
#define STAGE_TX (A_B + B_TX)        // 46080 B expect_tx
#define SMEM_DYN (1024 + NSTG * STAGE_SP)   // 189440 B

// ---------------------------------------------------------------------------
// Scratch (static device globals; no allocation allowed)
// ---------------------------------------------------------------------------
__device__ __half g_Khi16[(size_t)NN * NN];     // 128 MB: fp16-rounded K
__device__ __half g_Ph16[(size_t)MP * NN];      // scaled fp16 P, col-major
__device__ float  g_R[(size_t)MP * NN];
__device__ float  g_X[NN];
__device__ float  g_Vpart[(size_t)KSPLIT * MP * NN];  // 16 MB
__device__ float  g_alpha[PITER * MP];
__device__ float  g_beta[PITER * MP];
__device__ float  g_logdet;

// grid barrier state (self-resetting; g_gen monotonic across graph replays)
__device__ unsigned g_cnt = 0;
__device__ volatile unsigned g_gen = 0;

// ---------------------------------------------------------------------------
// PTX helpers (family-portable: ldmatrix / mma.sync / TMA / mbarrier)
// ---------------------------------------------------------------------------
__device__ __forceinline__ uint32_t smem_u32(const void* p) {
    uint32_t a;
    asm("{ .reg .u64 t; cvta.to.shared.u64 t, %1; cvt.u32.u64 %0, t; }"
        : "=r"(a) : "l"(p));
    return a;
}

__device__ __forceinline__ void ldsm_x4(uint32_t (&r)[4], uint32_t addr) {
    asm volatile("ldmatrix.sync.aligned.m8n8.x4.shared.b16 {%0,%1,%2,%3}, [%4];"
        : "=r"(r[0]), "=r"(r[1]), "=r"(r[2]), "=r"(r[3]) : "r"(addr));
}

__device__ __forceinline__ void mma16816(float (&d)[4], const uint32_t (&a)[4],
                                         uint32_t b0, uint32_t b1) {
    asm volatile("mma.sync.aligned.m16n8k16.row.col.f32.f16.f16.f32 "
        "{%0,%1,%2,%3}, {%4,%5,%6,%7}, {%8,%9}, {%0,%1,%2,%3};"
        : "+f"(d[0]), "+f"(d[1]), "+f"(d[2]), "+f"(d[3])
        : "r"(a[0]), "r"(a[1]), "r"(a[2]), "r"(a[3]), "r"(b0), "r"(b1));
}

#define MBAR_INIT(addr, cnt) \
    asm volatile("mbarrier.init.shared.b64 [%0], %1;" :: "r"(addr), "r"(cnt) : "memory")
#define MBAR_ARRIVE(addr) \
    asm volatile("mbarrier.arrive.shared.b64 _, [%0];" :: "r"(addr) : "memory")
#define MBAR_EXPECT_TX(addr, bytes) \
    asm volatile("mbarrier.arrive.expect_tx.shared.b64 _, [%0], %1;" \
                 :: "r"(addr), "r"(bytes) : "memory")

__device__ __forceinline__ void mbar_wait(uint32_t addr, uint32_t parity) {
    asm volatile(
        "{\n\t.reg .pred p;\n\t"
        "WAIT_%=:\n\t"
        "mbarrier.try_wait.parity.shared.b64 p, [%0], %1;\n\t"
        "@!p bra WAIT_%=;\n\t}"
        :: "r"(addr), "r"(parity) : "memory");
}

#define TMA2D(smem, map, x, y, mbar) \
    asm volatile("cp.async.bulk.tensor.2d.shared::cta.global.tile.mbarrier::complete_tx::bytes " \
                 "[%0], [%1, {%2, %3}], [%4];" \
                 :: "r"(smem), "l"(map), "r"(x), "r"(y), "r"(mbar) : "memory")

#define FENCE_ASYNC() asm volatile("fence.proxy.async.shared::cta;" ::: "memory")

// Swizzle matching CU_TENSOR_MAP_SWIZZLE_128B with 128B rows
// (r = row, ch = 16B chunk 0..7): byte_off ^ ((byte_off>>3)&0x70)
#define SWZ(r, ch) (((r) << 7) + ((((ch) ^ ((r) & 7))) << 4))

// ---------------------------------------------------------------------------
// Reductions
// ---------------------------------------------------------------------------
template <int BS>
__device__ __forceinline__ float blockReduce(float v, float* red) {
    int tid = threadIdx.x;
    red[tid] = v;
    __syncthreads();
#pragma unroll
    for (int s = BS / 2; s > 0; s >>= 1) {
        if (tid < s) red[tid] += red[tid + s];
        __syncthreads();
    }
    float out = red[0];
    __syncthreads();
    return out;
}

__device__ __forceinline__ float fastReduce512(float v, volatile float* red,
                                               volatile float* bc) {
    int lane = threadIdx.x & 31, wid = threadIdx.x >> 5;
#pragma unroll
    for (int o = 16; o > 0; o >>= 1) v += __shfl_xor_sync(0xFFFFFFFFu, v, o);
    if (lane == 0) red[wid] = v;
    __syncthreads();
    if (wid == 0) {
        float x = (lane < 16) ? red[lane] : 0.0f;
#pragma unroll
        for (int o = 8; o > 0; o >>= 1) x += __shfl_xor_sync(0xFFFFFFFFu, x, o);
        if (lane == 0) *bc = x;
    }
    __syncthreads();
    return *bc;
}

// ---------------------------------------------------------------------------
// Grid barrier: sense-reversing, self-resetting counter + monotonic gen flag.
// ---------------------------------------------------------------------------
__device__ __forceinline__ void gridSync(unsigned& gen) {
    __syncthreads();
    if (threadIdx.x == 0) {
        __threadfence();
        unsigned target = gen + 1;
        unsigned old = atomicAdd(&g_cnt, 1);
        if (old == NCTA - 1) {
            g_cnt = 0;
            __threadfence();
            g_gen = target;
        } else {
            while (g_gen != target) { __nanosleep(32); }
        }
        __threadfence();
        gen = target;
    }
    __syncthreads();
}

// ---------------------------------------------------------------------------
// Round K to fp16 (once per launch)
// ---------------------------------------------------------------------------
__global__ void k_split(const float* __restrict__ K) {
    size_t i0 = (size_t)blockIdx.x * blockDim.x + threadIdx.x;
    size_t stride = (size_t)gridDim.x * blockDim.x;
    size_t n8 = (size_t)NN * NN / 8;
    for (size_t i = i0; i < n8; i += stride) {
        float4 a = ((const float4*)K)[2 * i];
        float4 b = ((const float4*)K)[2 * i + 1];
        union { __half h[8]; uint4 u; } H;
        H.h[0] = __float2half_rn(a.x); H.h[1] = __float2half_rn(a.y);
        H.h[2] = __float2half_rn(a.z); H.h[3] = __float2half_rn(a.w);
        H.h[4] = __float2half_rn(b.x); H.h[5] = __float2half_rn(b.y);
        H.h[6] = __float2half_rn(b.z); H.h[7] = __float2half_rn(b.w);
        ((uint4*)g_Khi16)[i] = H.u;
    }
}

// ---------------------------------------------------------------------------
// Init: B = [y | Z | 0-pad]; P = fp16(B) (scale 1), R = B, X = 0
// ---------------------------------------------------------------------------
__global__ void k_init(const float* __restrict__ y, const float* __restrict__ Z) {
    int stride = gridDim.x * blockDim.x;
    for (int idx = blockIdx.x * blockDim.x + threadIdx.x; idx < MP * NN; idx += stride) {
        int col = idx >> 13;
        int row = idx & (NN - 1);
        float v = 0.0f;
        if (col == 0)        v = y[row];
        else if (col <= 100) v = Z[row * 100 + (col - 1)];
        g_Ph16[idx] = __float2half_rn(v);
        g_R[idx] = v;
        if (col == 0) g_X[row] = 0.0f;
    }
}

// ---------------------------------------------------------------------------
// Split TMA producers (single thread). F = global monotonic fill index.
// full barrier gets TWO expect_tx arrivals per phase (K part + B part).
// ---------------------------------------------------------------------------
__device__ __forceinline__ void produceK(uint32_t sb, int F, int t_in_it,
                                         int kbase, int rb,
                                         const CUtensorMap* mK, bool waitEmpty) {
    uint32_t s = (uint32_t)(F % NSTG);
    if (waitEmpty && F >= NSTG)
        mbar_wait(sb + 64 + s * 8, (uint32_t)((F / NSTG - 1) & 1));
    FENCE_ASYNC();
    uint32_t full = sb + s * 8;
    MBAR_EXPECT_TX(full, (uint32_t)A_B);
    uint32_t st = sb + 1024 + s * STAGE_SP;
    TMA2D(st, mK, kbase + t_in_it * KT, rb, full);
}

__device__ __forceinline__ void produceB(uint32_t sb, int F, int t_in_it,
                                         int kbase, const CUtensorMap* mB) {
    uint32_t s = (uint32_t)(F % NSTG);
    uint32_t full = sb + s * 8;
    MBAR_EXPECT_TX(full, (uint32_t)B_TX);
    uint32_t st = sb + 1024 + s * STAGE_SP;
    TMA2D(st + A_B, mB, kbase + t_in_it * KT, 0, full);
}

// ---------------------------------------------------------------------------
// Persistent kernel: 30 x (GEMM phase -> gridSync -> update phase -> gridSync)
// 128 CTAs x 512 threads (1/SM). GEMM: V = fp16(K) @ fp16(P), N=104 cols.
// ---------------------------------------------------------------------------
__global__ void __launch_bounds__(512) k_persist(
        const __grid_constant__ CUtensorMap tmK,
        const __grid_constant__ CUtensorMap tmB) {
    extern __shared__ __align__(1024) char smem[];
    uint32_t sb = smem_u32(smem);
    volatile float* red = (volatile float*)(smem + 128);   // 16 floats
    volatile float* bcp = (volatile float*)(smem + 256);

    int tid = threadIdx.x, lane = tid & 31, w = tid >> 5;
    int wm = w & 3, wn = w >> 2;
    int njmax = (wn == 3) ? 1 : 4;
    int bid = blockIdx.x;
    int rb = (bid & 31) * ROWB;
    int ksp = bid >> 5;
    int kbase = ksp * KCHUNK;

    // init mbarriers: full[s] count 2 (K + B expect_tx), empty[s] count 512
    if (tid == 0) {
#pragma unroll
        for (int s = 0; s < NSTG; s++) {
            MBAR_INIT(sb + s * 8, 2u);
            MBAR_INIT(sb + 64 + s * 8, 512u);
        }
    }
    __syncthreads();

    unsigned gen = g_gen;   // safe: read before any barrier can complete

    int rA = wm * 64 + (lane & 15);
    int rB = wn * 32 + (lane & 15);
    int chHalf = lane >> 4;

    // per-column CG state in registers (uniform across the CTA)
    float rs = 0.0f, csc = 1.0f;
    if (bid < MREAL) {
        const float4* R4 = (const float4*)(g_R + (size_t)bid * NN);
        float s = 0.0f;
#pragma unroll
        for (int t = 0; t < 4; t++) {
            float4 rv = R4[t * 512 + tid];
            s += rv.x * rv.x + rv.y * rv.y + rv.z * rv.z + rv.w * rv.w;
        }
        rs = fastReduce512(s, red, bcp);
    }
    __syncthreads();

    // prologue K fill for iteration 0 (buffers fresh -> no empty wait)
    if (tid == 0) {
#pragma unroll
        for (int s = 0; s < NSTG - 1; s++)
            produceK(sb, s, s, kbase, rb, &tmK, false);
    }

    for (int it = 0; it < PITER; it++) {
        int Fbase = it * KITERS;

        // B prologue: P is valid (post gridSync#2 of prev iter / k_init)
        if (tid == 0) {
#pragma unroll
            for (int s = 0; s < NSTG - 1; s++)
                produceB(sb, Fbase + s, s, kbase, &tmB);
        }

        // ------------------------------ GEMM phase ------------------------
        float acc[4][4][4];
#pragma unroll
        for (int mi = 0; mi < 4; mi++)
#pragma unroll
            for (int nj = 0; nj < 4; nj++)
#pragma unroll
                for (int q = 0; q < 4; q++) acc[mi][nj][q] = 0.0f;

        for (int t = 0; t < KITERS; t++) {
            int F = Fbase + t;
            if (tid == 0 && t + NSTG - 1 < KITERS) {
                produceK(sb, F + NSTG - 1, t + NSTG - 1, kbase, rb, &tmK, true);
                produceB(sb, F + NSTG - 1, t + NSTG - 1, kbase, &tmB);
            }

            uint32_t s = (uint32_t)(F % NSTG);
            mbar_wait(sb + s * 8, (uint32_t)((F / NSTG) & 1));
            uint32_t st = sb + 1024 + s * STAGE_SP;

#pragma unroll
            for (int kk = 0; kk < 4; kk++) {
                int ch = kk * 2 + chHalf;
                uint32_t ah[4][4], bh[2][4];
#pragma unroll
                for (int i = 0; i < 4; i++)
                    ldsm_x4(ah[i], st + SWZ(rA + i * 16, ch));
                ldsm_x4(bh[0], st + A_B + SWZ(rB, ch));
                if (wn < 3)
                    ldsm_x4(bh[1], st + A_B + SWZ(rB + 16, ch));
#pragma unroll
                for (int mi = 0; mi < 4; mi++)
#pragma unroll
                    for (int nj = 0; nj < 4; nj++) {
                        if (nj < njmax) {
                            int g = nj >> 1, sel = nj & 1;
                            mma16816(acc[mi][nj], ah[mi],
                                     bh[g][sel], bh[g][sel + 2]);
                        }
                    }
            }
            MBAR_ARRIVE(sb + 64 + s * 8);
        }

        // cross-iteration K prefetch: next iter's first stages (K only;
        // empty barriers for these stages already flipped this iteration)
        if (tid == 0 && it + 1 < PITER) {
            int Fn = (it + 1) * KITERS;
#pragma unroll
            for (int s = 0; s < NSTG - 1; s++)
                produceK(sb, Fn + s, s, kbase, rb, &tmK, true);
        }

        {   // epilogue: scatter fp32 accumulators to Vpart (col-major)
            float* vp = g_Vpart + (size_t)ksp * MP * NN;
            int row0 = rb + wm * 64 + (lane >> 2);
            int col0 = wn * 32 + (lane & 3) * 2;
#pragma unroll
            for (int mi = 0; mi < 4; mi++)
#pragma unroll
                for (int nj = 0; nj < 4; nj++) {
                    if (nj < njmax) {
                        int r_ = row0 + mi * 16;
                        int c_ = col0 + nj * 8;
                        vp[(size_t)c_ * NN + r_]           = acc[mi][nj][0];
                        vp[(size_t)(c_ + 1) * NN + r_]     = acc[mi][nj][1];
                        vp[(size_t)c_ * NN + r_ + 8]       = acc[mi][nj][2];
                        vp[(size_t)(c_ + 1) * NN + r_ + 8] = acc[mi][nj][3];
                    }
                }
        }

        gridSync(gen);   // Vpart complete before update reads it

        // ------------------------------ update phase ----------------------
        if (bid < MREAL) {
            int j = bid;
            const float4* V0 = (const float4*)g_Vpart + (size_t)j * NN / 4;
            const size_t PL = (size_t)MP * NN / 4;
            const float4* R4 = (const float4*)(g_R + (size_t)j * NN);
            const uint2* Ph2 = (const uint2*)(g_Ph16 + (size_t)j * NN);

            float4 p[4], v[4], r[4];
            float pv = 0.0f;
#pragma unroll
            for (int t = 0; t < 4; t++) {
                int i4 = t * 512 + tid;
                float4 a = __ldcg(V0 + i4);
                float4 b = __ldcg(V0 + PL + i4);
                float4 d2 = __ldcg(V0 + 2 * PL + i4);
                float4 e2 = __ldcg(V0 + 3 * PL + i4);
                float4 s = make_float4(a.x + b.x + d2.x + e2.x,
                                       a.y + b.y + d2.y + e2.y,
                                       a.z + b.z + d2.z + e2.z,
                                       a.w + b.w + d2.w + e2.w);
                v[t] = s;
                uint2 hu = Ph2[i4];
                __half2 h0 = *(__half2*)&hu.x, h1 = *(__half2*)&hu.y;
                float2 f0 = __half22float2(h0), f1 = __half22float2(h1);
                float4 pp = make_float4(f0.x, f0.y, f1.x, f1.y);
                p[t] = pp;
                pv += pp.x * s.x + pp.y * s.y + pp.z * s.z + pp.w * s.w;
            }
            pv = fastReduce512(pv, red, bcp);      // = c^2 * (P.V)
            float alpha = rs * csc * csc / pv;
            float aoc = alpha / csc;

            float rr = 0.0f;
#pragma unroll
            for (int t = 0; t < 4; t++) {
                int i4 = t * 512 + tid;
                float4 rv = R4[i4];
                rv.x -= aoc * v[t].x; rv.y -= aoc * v[t].y;
                rv.z -= aoc * v[t].z; rv.w -= aoc * v[t].w;
                r[t] = rv;
                rr += rv.x * rv.x + rv.y * rv.y + rv.z * rv.z + rv.w * rv.w;
            }
            if (j == 0) {
                float4* X4 = (float4*)g_X;
#pragma unroll
                for (int t = 0; t < 4; t++) {
                    int i4 = t * 512 + tid;
                    float4 x = X4[i4];
                    x.x += aoc * p[t].x; x.y += aoc * p[t].y;
                    x.z += aoc * p[t].z; x.w += aoc * p[t].w;
                    X4[i4] = x;
                }
            }
            rr = fastReduce512(rr, red, bcp);
            float beta = rr / rs;
            float c2 = exp2f(-rintf(0.5f * log2f(rr * (1.0f / (float)NN))));
            if (tid == 0) {
                g_alpha[it * MP + j] = alpha;
                g_beta[it * MP + j]  = beta;
            }
            float boc = beta / csc;

            uint2* Phw = (uint2*)(g_Ph16 + (size_t)j * NN);
            float4* Rw = (float4*)(g_R + (size_t)j * NN);
#pragma unroll
            for (int t = 0; t < 4; t++) {
                int i4 = t * 512 + tid;
                float pn[4] = {
                    r[t].x + boc * p[t].x, r[t].y + boc * p[t].y,
                    r[t].z + boc * p[t].z, r[t].w + boc * p[t].w };
                __half2 t0 = __floats2half2_rn(c2 * pn[0], c2 * pn[1]);
                __half2 t1 = __floats2half2_rn(c2 * pn[2], c2 * pn[3]);
                uint2 hu;
                hu.x = *(uint32_t*)&t0; hu.y = *(uint32_t*)&t1;
                Phw[i4] = hu;
                Rw[i4] = r[t];
            }
            rs = rr;
            csc = c2;
        }

        gridSync(gen);   // P complete before next GEMM's B loads / Vpart reuse
    }
}

// ---------------------------------------------------------------------------
// SLQ logdet (TQLI on 30x30 tridiagonal, first-row eigenvector weights)
// ---------------------------------------------------------------------------
__device__ void tqli30(double* d, double* e, double* z) {
    const int n = PITER;
    for (int l = 0; l < n; l++) {
        int iter = 0;
        int m;
        do {
            for (m = l; m < n - 1; m++) {
                double dd = fabs(d[m]) + fabs(d[m + 1]);
                if (fabs(e[m]) <= 2.3e-16 * dd) break;
            }
            if (m != l) {
                if (iter++ == 64) break;
                double g = (d[l + 1] - d[l]) / (2.0 * e[l]);
                double rr = sqrt(g * g + 1.0);
                double sg = (g >= 0.0) ? rr : -rr;
                g = d[m] - d[l] + e[l] / (g + sg);
                double s = 1.0, cc = 1.0, p = 0.0;
                bool under = false;
                for (int i = m - 1; i >= l; i--) {
                    double f = s * e[i];
                    double b = cc * e[i];
                    double rq = sqrt(f * f + g * g);
                    e[i + 1] = rq;
                    if (rq == 0.0) {
                        d[i + 1] -= p;
                        e[m] = 0.0;
                        under = true;
                        break;
                    }
                    s = f / rq; cc = g / rq;
                    g = d[i + 1] - p;
                    rq = (d[i] - g) * s + 2.0 * cc * b;
                    p = s * rq;
                    d[i + 1] = g + p;
                    g = cc * rq - b;
                    double zi = z[i], zi1 = z[i + 1];
                    z[i + 1] = s * zi + cc * zi1;
                    z[i]     = cc * zi - s * zi1;
                }
                if (under) continue;
                d[l] -= p;
                e[l] = g;
                e[m] = 0.0;
            }
        } while (m != l);
    }
}

__global__ void k_logdet() {
    __shared__ double qsum[128];
    int tid = threadIdx.x;
    double quad = 0.0;
    if (tid < 100) {
        int j = tid + 1;
        double d[PITER], e[PITER], z[PITER];
        double pa = 1.0, pb = 0.0;
        for (int k = 0; k < PITER; k++) {
            double a = (double)g_alpha[k * MP + j];
            double b = (double)g_beta[k * MP + j];
            d[k] = 1.0 / a + ((k > 0) ? pb / pa : 0.0);
            e[k] = (k < PITER - 1) ? sqrt(b) / a : 0.0;
            z[k] = (k == 0) ? 1.0 : 0.0;
            pa = a; pb = b;
        }
        tqli30(d, e, z);
        for (int k = 0; k < PITER; k++) {
            double lam = d[k] < 1e-12 ? 1e-12 : d[k];
            quad += z[k] * z[k] * log(lam);
        }
    }
    qsum[tid] = quad;
    __syncthreads();
    if (tid == 0) {
        double s = 0.0;
        for (int i = 0; i < 100; i++) s += qsum[i];
        g_logdet = (float)((double)NN * s / 100.0);
    }
}

__global__ void k_final(const float* __restrict__ y, float* __restrict__ out) {
    __shared__ float red[256];
    float s = 0.0f;
    for (int i = threadIdx.x; i < NN; i += 256) s += y[i] * g_X[i];
    s = blockReduce<256>(s, red);
    if (threadIdx.x == 0) {
        const double LOG2PI = 1.8378770664093454836;
        double r = -0.5 * (double)s - 0.5 * (double)g_logdet - 0.5 * (double)NN * LOG2PI;
        out[0] = (float)r;
    }
}

// ---------------------------------------------------------------------------
// Launch: build TensorMaps via driver entry point (cudart-only), then chain.
// ---------------------------------------------------------------------------
typedef CUresult (*PFN_encodeTiled)(
    CUtensorMap*, CUtensorMapDataType, cuuint32_t, void*,
    const cuuint64_t*, const cuuint64_t*, const cuuint32_t*, const cuuint32_t*,
    CUtensorMapInterleave, CUtensorMapSwizzle, CUtensorMapL2promotion,
    CUtensorMapFloatOOBfill);

extern "C" void kernel_launch(void* const* d_in, const int* in_sizes, int n_in,
                              void* d_out, int out_size) {
    const float* K = (const float*)d_in[0];
    const float* y = (const float*)d_in[1];
    const float* Z = (const float*)d_in[2];
    float* out = (float*)d_out;

    // resolve cuTensorMapEncodeTiled through cudart (no -lcuda needed)
    void* fn = nullptr;
    cudaDriverEntryPointQueryResult qres;
    cudaGetDriverEntryPointByVersion("cuTensorMapEncodeTiled", &fn, 12000,
                                     cudaEnableDefault, &qres);
    PFN_encodeTiled enc = (PFN_encodeTiled)fn;

    void *pK = nullptr, *pPh = nullptr;
    cudaGetSymbolAddress(&pK, g_Khi16);
    cudaGetSymbolAddress(&pPh, g_Ph16);

    CUtensorMap tmK, tmB;
    {
        cuuint64_t dims[2] = {NN, NN};
        cuuint64_t strides[1] = {NN * 2};
        cuuint32_t box[2] = {64, 256};
        cuuint32_t es[2] = {1, 1};
        enc(&tmK, CU_TENSOR_MAP_DATA_TYPE_FLOAT16, 2, pK, dims, strides, box, es,
            CU_TENSOR_MAP_INTERLEAVE_NONE, CU_TENSOR_MAP_SWIZZLE_128B,
            CU_TENSOR_MAP_L2_PROMOTION_L2_128B, CU_TENSOR_MAP_FLOAT_OOB_FILL_NONE);
    }
    {
        cuuint64_t dims[2] = {NN, MP};
        cuuint64_t strides[1] = {NN * 2};
        cuuint32_t box[2] = {64, NCOLS};
        cuuint32_t es[2] = {1, 1};
        enc(&tmB, CU_TENSOR_MAP_DATA_TYPE_FLOAT16, 2, pPh, dims, strides, box, es,
            CU_TENSOR_MAP_INTERLEAVE_NONE, CU_TENSOR_MAP_SWIZZLE_128B,
            CU_TENSOR_MAP_L2_PROMOTION_L2_128B, CU_TENSOR_MAP_FLOAT_OOB_FILL_NONE);
    }

    cudaFuncSetAttribute(k_persist, cudaFuncAttributeMaxDynamicSharedMemorySize,
                         SMEM_DYN);

    k_split<<<4096, 256>>>(K);
    k_init<<<512, 256>>>(y, Z);
    k_persist<<<NCTA, 512, SMEM_DYN>>>(tmK, tmB);
    k_logdet<<<1, 128>>>();
    k_final<<<1, 256>>>(y, out);
}